// round 8
// baseline (speedup 1.0000x reference)
#include <cuda_runtime.h>
#include <math.h>

#define NN 10000
#define EE 640000
#define F  64
#define EFD 16

typedef unsigned long long u64p;

// ---- scratch (device globals; no allocations allowed) ----
__device__ float g_Asrc[NN*F];
__device__ float g_Adst[NN*F];
__device__ float g_Kn[NN*F];
__device__ float g_Qn[NN*F];
__device__ float g_Qk[NN*EFD];
__device__ float g_qd2[NN];
__device__ float g_denom[NN];
__device__ float g_hneigh[NN*F];
__device__ float g_e[EE];      // holds exp(score) after K1
__device__ float g_dist[EE];

__device__ __forceinline__ float siluf(float x) { return x / (1.f + __expf(-x)); }

__device__ __forceinline__ void redAdd4(float* addr, float a, float b, float c, float d) {
    asm volatile("red.global.add.v4.f32 [%0], {%1,%2,%3,%4};"
                 :: "l"(addr), "f"(a), "f"(b), "f"(c), "f"(d) : "memory");
}

__device__ __forceinline__ u64p pack2(float x, float y) {
    u64p r; asm("mov.b64 %0, {%1,%2};" : "=l"(r) : "f"(x), "f"(y)); return r;
}
__device__ __forceinline__ void unpack2(u64p v, float& x, float& y) {
    asm("mov.b64 {%0,%1}, %2;" : "=f"(x), "=f"(y) : "l"(v));
}
__device__ __forceinline__ void ffma2(u64p& d, u64p a, u64p b) {
    asm("fma.rn.f32x2 %0, %1, %2, %0;" : "+l"(d) : "l"(a), "l"(b));
}

// ================= K0: per-node precompute + init =================
__global__ void k0_node_pre(const float* __restrict__ nf,
                            const float* __restrict__ We1,
                            const float* __restrict__ Wk,
                            const float* __restrict__ Wq) {
    __shared__ __align__(16) float srow[4 * F];
    __shared__ __align__(16) float sQ[4 * F];
    int tid = threadIdx.x;
    int nodeBase = blockIdx.x * 4;
    srow[tid] = nf[(size_t)nodeBase * F + tid];
    __syncthreads();
    int ln = tid >> 6;
    int c  = tid & 63;
    int node = nodeBase + ln;
    const float* r = srow + ln * F;
    float a0 = 0.f, a1 = 0.f, a2 = 0.f, a3 = 0.f;
#pragma unroll 8
    for (int k = 0; k < F; ++k) {
        float x = r[k];
        a0 += x * __ldg(We1 + k * F + c);
        a1 += x * __ldg(We1 + (F + k) * F + c);
        a2 += x * __ldg(Wk  + k * F + c);
        a3 += x * __ldg(Wq  + k * F + c);
    }
    g_Asrc[node * F + c] = a0;
    g_Adst[node * F + c] = a1;
    g_Kn  [node * F + c] = a2;
    g_Qn  [node * F + c] = a3;
    sQ[ln * F + c] = a3;
    g_hneigh[node * F + c] = 0.f;
    if (c == 0) g_denom[node] = 0.f;
    __syncthreads();
    if (tid < 64) {
        int ln2 = tid >> 4, j = tid & 15;
        const float* q = sQ + ln2 * F;
        float acc = 0.f;
#pragma unroll 8
        for (int k = 0; k < F; ++k) acc += q[k] * __ldg(Wk + (65 + j) * F + k);
        g_Qk[(nodeBase + ln2) * EFD + j] = acc;
    } else if (tid < 68) {
        int ln2 = tid - 64;
        const float* q = sQ + ln2 * F;
        float acc = 0.f;
#pragma unroll 8
        for (int k = 0; k < F; ++k) acc += q[k] * __ldg(Wk + 64 * F + k);
        g_qd2[nodeBase + ln2] = acc;
    }
}

// ================= K1: edge scores -> exp(e), denom atomicAdd =================
__global__ void __launch_bounds__(256)
k1_scores(const float* __restrict__ coord,
          const float* __restrict__ efeat,
          const int* __restrict__ src,
          const int* __restrict__ dst) {
    int tid = threadIdx.x;
    int warp = tid >> 5, lane = tid & 31;
    int sub = lane >> 4, c = lane & 15;
    int base = blockIdx.x * 128 + warp * 16;

#pragma unroll
    for (int it = 0; it < 8; ++it) {
        int e = base + it * 2 + sub;
        int s = __ldg(&src[e]);
        int d = __ldg(&dst[e]);

        float4 kv = __ldg((const float4*)(g_Kn + (size_t)s * F) + c);
        float4 qv = __ldg((const float4*)(g_Qn + (size_t)d * F) + c);
        float part = kv.x * qv.x + kv.y * qv.y + kv.z * qv.z + kv.w * qv.w;

        if (c < 4) {
            float4 ev = __ldg((const float4*)(efeat + (size_t)e * EFD) + c);
            float4 qk = __ldg((const float4*)(g_Qk + (size_t)d * EFD) + c);
            part += ev.x * qk.x + ev.y * qk.y + ev.z * qk.z + ev.w * qk.w;
        }

        float dist = 0.f;
        if (c == 0) {
            float dx = __ldg(&coord[s * 3 + 0]) - __ldg(&coord[d * 3 + 0]);
            float dy = __ldg(&coord[s * 3 + 1]) - __ldg(&coord[d * 3 + 1]);
            float dz = __ldg(&coord[s * 3 + 2]) - __ldg(&coord[d * 3 + 2]);
            dist = sqrtf(dx * dx + dy * dy + dz * dz);
            part += dist * __ldg(&g_qd2[d]);
        }

#pragma unroll
        for (int o = 8; o; o >>= 1)
            part += __shfl_down_sync(0xffffffffu, part, o, 16);

        if (c == 0) {
            float v = __expf(part * 0.125f);
            g_e[e] = v;
            g_dist[e] = dist;
            atomicAdd(&g_denom[d], v);
        }
    }
}

// ================= K3: in-place staged edge-message GEMM + scatter =================
// Block = 256 threads, 128 edges, 4 blocks/SM (55.8KB smem).
// SCR union [16 groups][stride 516]:
//  - gather writes Asrc[s]+Adst[d] as [h4][e][4]
//  - Phase A rewrites h1 IN PLACE (efeat via direct LDG)
//  - Phase B GEMM tile 2e x 16c reads it
//  - epilogue rewrites silu*att as [c4][e][4] (same layout family)
//  - scatter reads [c4][e][4] coalesced -> red.global.add.v4
#define EPB 128
#define GSTRIDE 516
#define SM_SCR   0            // 16*516 = 8256
#define SM_WE2   8256         // 4096
#define SM_WEE1  12352        // 1024
#define SM_W1D   13376        // 64
#define SM_B1    13440        // 64
#define SM_B2    13504        // 64
#define SM_ATT   13568        // 128
#define SM_DIST  13696        // 128
#define SM_DSTI  13824        // 128 ints
#define SM_FLOATS 13952

__global__ void __launch_bounds__(256, 4)
k3_message(const float* __restrict__ efeat,
           const float* __restrict__ We1,
           const float* __restrict__ be1,
           const float* __restrict__ We2,
           const float* __restrict__ be2,
           const int* __restrict__ src,
           const int* __restrict__ dst) {
    extern __shared__ __align__(16) float sm[];
    float* sSCR   = sm + SM_SCR;
    float* sWe2   = sm + SM_WE2;
    float* sWee1t = sm + SM_WEE1;
    float* sW1d   = sm + SM_W1D;
    float* sB1    = sm + SM_B1;
    float* sB2    = sm + SM_B2;
    float* sAtt   = sm + SM_ATT;
    float* sDist  = sm + SM_DIST;
    int*   sDstA  = (int*)(sm + SM_DSTI);

    int tid = threadIdx.x;
    int blockbase = blockIdx.x * EPB;

    // ---- prestage weights + per-edge scalars ----
    for (int i = tid; i < F * F; i += 256) sWe2[i] = We2[i];
    for (int i = tid; i < F * EFD; i += 256) {
        int h = i / EFD, j = i % EFD;
        sWee1t[i] = We1[(129 + j) * F + h];
    }
    if (tid < F) { sW1d[tid] = We1[128 * F + tid]; sB1[tid] = be1[tid]; sB2[tid] = be2[tid]; }
    if (tid >= 128 && tid < 256) {
        int e = blockbase + tid - 128;
        int d = __ldg(&dst[e]);
        sDstA[tid - 128] = d;
        sAtt[tid - 128] = __fdividef(__ldg(&g_e[e]), __ldg(&g_denom[d]));
        sDist[tid - 128] = __ldg(&g_dist[e]);
    }

    // ---- coalesced gather of Asrc[s]+Adst[d] directly into [h4][e][4] ----
#pragma unroll
    for (int it = 0; it < 8; ++it) {
        int item = it * 256 + tid;   // 0..2047
        int e = item >> 4;
        int c = item & 15;           // h4 group
        int s = __ldg(&src[blockbase + e]);
        int d = __ldg(&dst[blockbase + e]);
        float4 a = __ldg((const float4*)(g_Asrc + (size_t)s * F) + c);
        float4 b = __ldg((const float4*)(g_Adst + (size_t)d * F) + c);
        *(float4*)(sSCR + c * GSTRIDE + e * 4) =
            make_float4(a.x + b.x, a.y + b.y, a.z + b.z, a.w + b.w);
    }
    __syncthreads();

    // ---------------- Phase A: h1 in place, 2 threads/edge ----------------
    {
        int etid = tid & 127;
        int half = tid >> 7;
        float dist = sDist[etid];
        const float4* efp = (const float4*)(efeat + (size_t)(blockbase + etid) * EFD);
        float4 q0 = __ldg(efp + 0), q1 = __ldg(efp + 1), q2 = __ldg(efp + 2), q3 = __ldg(efp + 3);
        u64p epk[8];
        epk[0] = pack2(q0.x, q0.y); epk[1] = pack2(q0.z, q0.w);
        epk[2] = pack2(q1.x, q1.y); epk[3] = pack2(q1.z, q1.w);
        epk[4] = pack2(q2.x, q2.y); epk[5] = pack2(q2.z, q2.w);
        epk[6] = pack2(q3.x, q3.y); epk[7] = pack2(q3.z, q3.w);

#pragma unroll 2
        for (int g = 0; g < 8; ++g) {
            int h4 = half * 8 + g;
            float* slot = sSCR + h4 * GSTRIDE + etid * 4;
            float4 ab = *(const float4*)slot;
            float4 wd = ((const float4*)sW1d)[h4];
            float4 b1 = ((const float4*)sB1)[h4];
            float pre[4], out[4];
            pre[0] = ab.x + dist * wd.x + b1.x;
            pre[1] = ab.y + dist * wd.y + b1.y;
            pre[2] = ab.z + dist * wd.z + b1.z;
            pre[3] = ab.w + dist * wd.w + b1.w;
#pragma unroll
            for (int kk = 0; kk < 4; ++kk) {
                int h = h4 * 4 + kk;
                const ulonglong2* wt = (const ulonglong2*)(sWee1t + h * EFD);
                ulonglong2 wA = wt[0], wB = wt[1];
                u64p acc2 = 0ULL;
                ffma2(acc2, epk[0], wA.x); ffma2(acc2, epk[1], wA.y);
                ffma2(acc2, epk[2], wB.x); ffma2(acc2, epk[3], wB.y);
                ulonglong2 wC = wt[2], wD = wt[3];
                ffma2(acc2, epk[4], wC.x); ffma2(acc2, epk[5], wC.y);
                ffma2(acc2, epk[6], wD.x); ffma2(acc2, epk[7], wD.y);
                float lo, hi; unpack2(acc2, lo, hi);
                out[kk] = siluf(pre[kk] + lo + hi);
            }
            *(float4*)slot = make_float4(out[0], out[1], out[2], out[3]);
        }
    }
    __syncthreads();

    // ---------------- Phase B: packed GEMM, tile 2e x 16c ----------------
    int et = tid & 63;   // edges 2et, 2et+1
    int ct = tid >> 6;   // channels [ct*16, ct*16+16)

    u64p acc[2][8];
    {
        const ulonglong2* b2p = (const ulonglong2*)(sB2 + ct * 16);
        ulonglong2 b0 = b2p[0], b1v = b2p[1], b2v = b2p[2], b3v = b2p[3];
        acc[0][0] = b0.x;  acc[0][1] = b0.y;  acc[0][2] = b1v.x; acc[0][3] = b1v.y;
        acc[0][4] = b2v.x; acc[0][5] = b2v.y; acc[0][6] = b3v.x; acc[0][7] = b3v.y;
#pragma unroll
        for (int i = 0; i < 8; ++i) acc[1][i] = acc[0][i];
    }

    const float* wbase = sWe2 + ct * 16;
#pragma unroll 4
    for (int h4 = 0; h4 < 16; ++h4) {
        const float* gb = sSCR + h4 * GSTRIDE + et * 8;
        float4 fa = *(const float4*)gb;        // edge 2et
        float4 fb = *(const float4*)(gb + 4);  // edge 2et+1
        float ea[4] = { fa.x, fa.y, fa.z, fa.w };
        float eb[4] = { fb.x, fb.y, fb.z, fb.w };
#pragma unroll
        for (int j = 0; j < 4; ++j) {
            const ulonglong2* w = (const ulonglong2*)(wbase + (h4 * 4 + j) * F);
            ulonglong2 wA = w[0], wB = w[1], wC = w[2], wD = w[3];
            u64p ha = pack2(ea[j], ea[j]);
            u64p hb = pack2(eb[j], eb[j]);
            ffma2(acc[0][0], ha, wA.x); ffma2(acc[0][1], ha, wA.y);
            ffma2(acc[0][2], ha, wB.x); ffma2(acc[0][3], ha, wB.y);
            ffma2(acc[0][4], ha, wC.x); ffma2(acc[0][5], ha, wC.y);
            ffma2(acc[0][6], ha, wD.x); ffma2(acc[0][7], ha, wD.y);
            ffma2(acc[1][0], hb, wA.x); ffma2(acc[1][1], hb, wA.y);
            ffma2(acc[1][2], hb, wB.x); ffma2(acc[1][3], hb, wB.y);
            ffma2(acc[1][4], hb, wC.x); ffma2(acc[1][5], hb, wC.y);
            ffma2(acc[1][6], hb, wD.x); ffma2(acc[1][7], hb, wD.y);
        }
    }
    __syncthreads();   // all Phase-B reads of SCR done before epilogue overwrites

    // ---- epilogue: silu*att into SCR as [c4][e][4] ----
#pragma unroll
    for (int ee = 0; ee < 2; ++ee) {
        int el = et * 2 + ee;
        float att = sAtt[el];
#pragma unroll
        for (int q = 0; q < 4; ++q) {
            float v0, v1, v2, v3;
            unpack2(acc[ee][2 * q],     v0, v1);
            unpack2(acc[ee][2 * q + 1], v2, v3);
            *(float4*)(sSCR + (ct * 4 + q) * GSTRIDE + el * 4) =
                make_float4(siluf(v0) * att, siluf(v1) * att,
                            siluf(v2) * att, siluf(v3) * att);
        }
    }
    __syncthreads();

    // ---- coalesced REDG scatter ----
#pragma unroll
    for (int it = 0; it < 8; ++it) {
        int item = it * 256 + tid;   // 0..2047
        int e = item >> 4;
        int c = item & 15;
        float4 v = *(const float4*)(sSCR + c * GSTRIDE + e * 4);
        redAdd4(g_hneigh + (size_t)sDstA[e] * F + c * 4, v.x, v.y, v.z, v.w);
    }
}

// ================= K4: node MLP (4-way ILP) =================
__global__ void k4_node(const float* __restrict__ nf,
                        const float* __restrict__ Wn1,
                        const float* __restrict__ bn1,
                        const float* __restrict__ Wn2,
                        const float* __restrict__ bn2,
                        float* __restrict__ out) {
    __shared__ __align__(16) float sh1[4 * F];
    int tid = threadIdx.x;
    int ln = tid >> 6, c = tid & 63;
    int node = blockIdx.x * 4 + ln;

    const float4* nfr = (const float4*)(nf + (size_t)node * F);
    const float4* hr  = (const float4*)(g_hneigh + (size_t)node * F);

    float accs[4] = { bn1[c], 0.f, 0.f, 0.f };
#pragma unroll
    for (int k4 = 0; k4 < 16; ++k4) {
        float4 x = __ldg(nfr + k4);
        float a = accs[k4 & 3];
        a += x.x * __ldg(Wn1 + (k4 * 4 + 0) * F + c);
        a += x.y * __ldg(Wn1 + (k4 * 4 + 1) * F + c);
        a += x.z * __ldg(Wn1 + (k4 * 4 + 2) * F + c);
        a += x.w * __ldg(Wn1 + (k4 * 4 + 3) * F + c);
        accs[k4 & 3] = a;
    }
#pragma unroll
    for (int k4 = 0; k4 < 16; ++k4) {
        float4 x = hr[k4];
        float a = accs[k4 & 3];
        a += x.x * __ldg(Wn1 + (F + k4 * 4 + 0) * F + c);
        a += x.y * __ldg(Wn1 + (F + k4 * 4 + 1) * F + c);
        a += x.z * __ldg(Wn1 + (F + k4 * 4 + 2) * F + c);
        a += x.w * __ldg(Wn1 + (F + k4 * 4 + 3) * F + c);
        accs[k4 & 3] = a;
    }
    sh1[ln * F + c] = siluf((accs[0] + accs[1]) + (accs[2] + accs[3]));
    __syncthreads();

    const float* h1r = sh1 + ln * F;
    float os[4] = { bn2[c], 0.f, 0.f, 0.f };
#pragma unroll
    for (int k4 = 0; k4 < 16; ++k4) {
        float o = os[k4 & 3];
        o += h1r[k4 * 4 + 0] * __ldg(Wn2 + (k4 * 4 + 0) * F + c);
        o += h1r[k4 * 4 + 1] * __ldg(Wn2 + (k4 * 4 + 1) * F + c);
        o += h1r[k4 * 4 + 2] * __ldg(Wn2 + (k4 * 4 + 2) * F + c);
        o += h1r[k4 * 4 + 3] * __ldg(Wn2 + (k4 * 4 + 3) * F + c);
        os[k4 & 3] = o;
    }
    out[(size_t)node * F + c] = (os[0] + os[1]) + (os[2] + os[3]);
}

extern "C" void kernel_launch(void* const* d_in, const int* in_sizes, int n_in,
                              void* d_out, int out_size) {
    const float* nf    = (const float*)d_in[0];
    const float* coord = (const float*)d_in[1];
    const float* efeat = (const float*)d_in[2];
    const float* We1   = (const float*)d_in[3];
    const float* be1   = (const float*)d_in[4];
    const float* We2   = (const float*)d_in[5];
    const float* be2   = (const float*)d_in[6];
    const float* Wn1   = (const float*)d_in[7];
    const float* bn1   = (const float*)d_in[8];
    const float* Wn2   = (const float*)d_in[9];
    const float* bn2   = (const float*)d_in[10];
    const float* Wq    = (const float*)d_in[11];
    const float* Wk    = (const float*)d_in[12];
    const int*   src   = (const int*)d_in[13];
    const int*   dst   = (const int*)d_in[14];
    float* out = (float*)d_out;

    const int k3_smem = SM_FLOATS * (int)sizeof(float);
    cudaFuncSetAttribute(k3_message, cudaFuncAttributeMaxDynamicSharedMemorySize, k3_smem);

    k0_node_pre<<<NN / 4, 256>>>(nf, We1, Wk, Wq);
    k1_scores<<<EE / 128, 256>>>(coord, efeat, src, dst);
    k3_message<<<EE / EPB, 256, k3_smem>>>(efeat, We1, be1, We2, be2, src, dst);
    k4_node<<<NN / 4, 256>>>(nf, Wn1, bn1, Wn2, bn2, out);
}

// round 9
// speedup vs baseline: 1.0676x; 1.0676x over previous
#include <cuda_runtime.h>
#include <math.h>

#define NN 10000
#define EE 640000
#define F  64
#define EFD 16

typedef unsigned long long u64p;

// ---- scratch (device globals; no allocations allowed) ----
__device__ float g_Asrc[NN*F];
__device__ float g_Adst[NN*F];
__device__ float g_Kn[NN*F];
__device__ float g_Qn[NN*F];
__device__ float g_Qk[NN*EFD];
__device__ float g_qd2[NN];
__device__ float g_denom[NN];
__device__ float g_hneigh[NN*F];
__device__ float g_e[EE];      // holds exp(score) after K1
__device__ float g_dist[EE];

__device__ __forceinline__ float siluf(float x) { return x / (1.f + __expf(-x)); }

__device__ __forceinline__ void redAdd4(float* addr, float a, float b, float c, float d) {
    asm volatile("red.global.add.v4.f32 [%0], {%1,%2,%3,%4};"
                 :: "l"(addr), "f"(a), "f"(b), "f"(c), "f"(d) : "memory");
}

__device__ __forceinline__ u64p pack2(float x, float y) {
    u64p r; asm("mov.b64 %0, {%1,%2};" : "=l"(r) : "f"(x), "f"(y)); return r;
}
__device__ __forceinline__ void unpack2(u64p v, float& x, float& y) {
    asm("mov.b64 {%0,%1}, %2;" : "=f"(x), "=f"(y) : "l"(v));
}
__device__ __forceinline__ void ffma2(u64p& d, u64p a, u64p b) {
    asm("fma.rn.f32x2 %0, %1, %2, %0;" : "+l"(d) : "l"(a), "l"(b));
}

// ================= K0: per-node precompute + init =================
__global__ void k0_node_pre(const float* __restrict__ nf,
                            const float* __restrict__ We1,
                            const float* __restrict__ Wk,
                            const float* __restrict__ Wq) {
    __shared__ __align__(16) float srow[4 * F];
    __shared__ __align__(16) float sQ[4 * F];
    int tid = threadIdx.x;
    int nodeBase = blockIdx.x * 4;
    srow[tid] = nf[(size_t)nodeBase * F + tid];
    __syncthreads();
    int ln = tid >> 6;
    int c  = tid & 63;
    int node = nodeBase + ln;
    const float* r = srow + ln * F;
    float a0 = 0.f, a1 = 0.f, a2 = 0.f, a3 = 0.f;
#pragma unroll 8
    for (int k = 0; k < F; ++k) {
        float x = r[k];
        a0 += x * __ldg(We1 + k * F + c);
        a1 += x * __ldg(We1 + (F + k) * F + c);
        a2 += x * __ldg(Wk  + k * F + c);
        a3 += x * __ldg(Wq  + k * F + c);
    }
    g_Asrc[node * F + c] = a0;
    g_Adst[node * F + c] = a1;
    g_Kn  [node * F + c] = a2;
    g_Qn  [node * F + c] = a3;
    sQ[ln * F + c] = a3;
    g_hneigh[node * F + c] = 0.f;
    if (c == 0) g_denom[node] = 0.f;
    __syncthreads();
    if (tid < 64) {
        int ln2 = tid >> 4, j = tid & 15;
        const float* q = sQ + ln2 * F;
        float acc = 0.f;
#pragma unroll 8
        for (int k = 0; k < F; ++k) acc += q[k] * __ldg(Wk + (65 + j) * F + k);
        g_Qk[(nodeBase + ln2) * EFD + j] = acc;
    } else if (tid < 68) {
        int ln2 = tid - 64;
        const float* q = sQ + ln2 * F;
        float acc = 0.f;
#pragma unroll 8
        for (int k = 0; k < F; ++k) acc += q[k] * __ldg(Wk + 64 * F + k);
        g_qd2[nodeBase + ln2] = acc;
    }
}

// ================= K1: edge scores -> exp(e), denom atomicAdd =================
__global__ void __launch_bounds__(256)
k1_scores(const float* __restrict__ coord,
          const float* __restrict__ efeat,
          const int* __restrict__ src,
          const int* __restrict__ dst) {
    int tid = threadIdx.x;
    int warp = tid >> 5, lane = tid & 31;
    int sub = lane >> 4, c = lane & 15;
    int base = blockIdx.x * 128 + warp * 16;

#pragma unroll
    for (int it = 0; it < 8; ++it) {
        int e = base + it * 2 + sub;
        int s = __ldg(&src[e]);
        int d = __ldg(&dst[e]);

        float4 kv = __ldg((const float4*)(g_Kn + (size_t)s * F) + c);
        float4 qv = __ldg((const float4*)(g_Qn + (size_t)d * F) + c);
        float part = kv.x * qv.x + kv.y * qv.y + kv.z * qv.z + kv.w * qv.w;

        if (c < 4) {
            float4 ev = __ldg((const float4*)(efeat + (size_t)e * EFD) + c);
            float4 qk = __ldg((const float4*)(g_Qk + (size_t)d * EFD) + c);
            part += ev.x * qk.x + ev.y * qk.y + ev.z * qk.z + ev.w * qk.w;
        }

        float dist = 0.f;
        if (c == 0) {
            float dx = __ldg(&coord[s * 3 + 0]) - __ldg(&coord[d * 3 + 0]);
            float dy = __ldg(&coord[s * 3 + 1]) - __ldg(&coord[d * 3 + 1]);
            float dz = __ldg(&coord[s * 3 + 2]) - __ldg(&coord[d * 3 + 2]);
            dist = sqrtf(dx * dx + dy * dy + dz * dz);
            part += dist * __ldg(&g_qd2[d]);
        }

#pragma unroll
        for (int o = 8; o; o >>= 1)
            part += __shfl_down_sync(0xffffffffu, part, o, 16);

        if (c == 0) {
            float v = __expf(part * 0.125f);
            g_e[e] = v;
            g_dist[e] = dist;
            atomicAdd(&g_denom[d], v);
        }
    }
}

// ================= K3: in-place staged edge-message GEMM + scatter =================
// Block = 256 threads, 128 edges, 55.8KB smem -> 4 blocks/SM.
// SCR union [16 groups][stride 516]:
//  - gather writes Asrc[s]+Adst[d] as [h4][e][4]
//  - Phase A rewrites h1 IN PLACE (efeat via direct LDG)
//  - Phase B GEMM tile 4e x 8c (strided edges et,+32,+64,+96) reads it
//  - epilogue rewrites silu*att as [c4][e][4] (same layout family)
//  - scatter reads [c4][e][4] coalesced -> red.global.add.v4
#define EPB 128
#define GSTRIDE 516
#define SM_SCR   0            // 16*516 = 8256
#define SM_WE2   8256         // 4096
#define SM_WEE1  12352        // 1024
#define SM_W1D   13376        // 64
#define SM_B1    13440        // 64
#define SM_B2    13504        // 64
#define SM_ATT   13568        // 128
#define SM_DIST  13696        // 128
#define SM_DSTI  13824        // 128 ints
#define SM_FLOATS 13952

__global__ void __launch_bounds__(256, 4)
k3_message(const float* __restrict__ efeat,
           const float* __restrict__ We1,
           const float* __restrict__ be1,
           const float* __restrict__ We2,
           const float* __restrict__ be2,
           const int* __restrict__ src,
           const int* __restrict__ dst) {
    extern __shared__ __align__(16) float sm[];
    float* sSCR   = sm + SM_SCR;
    float* sWe2   = sm + SM_WE2;
    float* sWee1t = sm + SM_WEE1;
    float* sW1d   = sm + SM_W1D;
    float* sB1    = sm + SM_B1;
    float* sB2    = sm + SM_B2;
    float* sAtt   = sm + SM_ATT;
    float* sDist  = sm + SM_DIST;
    int*   sDstA  = (int*)(sm + SM_DSTI);

    int tid = threadIdx.x;
    int blockbase = blockIdx.x * EPB;

    // ---- prestage weights + per-edge scalars ----
    for (int i = tid; i < F * F; i += 256) sWe2[i] = We2[i];
    for (int i = tid; i < F * EFD; i += 256) {
        int h = i / EFD, j = i % EFD;
        sWee1t[i] = We1[(129 + j) * F + h];
    }
    if (tid < F) { sW1d[tid] = We1[128 * F + tid]; sB1[tid] = be1[tid]; sB2[tid] = be2[tid]; }
    if (tid >= 128 && tid < 256) {
        int e = blockbase + tid - 128;
        int d = __ldg(&dst[e]);
        sDstA[tid - 128] = d;
        sAtt[tid - 128] = __fdividef(__ldg(&g_e[e]), __ldg(&g_denom[d]));
        sDist[tid - 128] = __ldg(&g_dist[e]);
    }

    // ---- coalesced gather of Asrc[s]+Adst[d] directly into [h4][e][4] ----
#pragma unroll
    for (int it = 0; it < 8; ++it) {
        int item = it * 256 + tid;   // 0..2047
        int e = item >> 4;
        int c = item & 15;           // h4 group
        int s = __ldg(&src[blockbase + e]);
        int d = __ldg(&dst[blockbase + e]);
        float4 a = __ldg((const float4*)(g_Asrc + (size_t)s * F) + c);
        float4 b = __ldg((const float4*)(g_Adst + (size_t)d * F) + c);
        *(float4*)(sSCR + c * GSTRIDE + e * 4) =
            make_float4(a.x + b.x, a.y + b.y, a.z + b.z, a.w + b.w);
    }
    __syncthreads();

    // ---------------- Phase A: h1 in place, 2 threads/edge ----------------
    {
        int etid = tid & 127;
        int half = tid >> 7;
        float dist = sDist[etid];
        const float4* efp = (const float4*)(efeat + (size_t)(blockbase + etid) * EFD);
        float4 q0 = __ldg(efp + 0), q1 = __ldg(efp + 1), q2 = __ldg(efp + 2), q3 = __ldg(efp + 3);
        u64p epk[8];
        epk[0] = pack2(q0.x, q0.y); epk[1] = pack2(q0.z, q0.w);
        epk[2] = pack2(q1.x, q1.y); epk[3] = pack2(q1.z, q1.w);
        epk[4] = pack2(q2.x, q2.y); epk[5] = pack2(q2.z, q2.w);
        epk[6] = pack2(q3.x, q3.y); epk[7] = pack2(q3.z, q3.w);

#pragma unroll 2
        for (int g = 0; g < 8; ++g) {
            int h4 = half * 8 + g;
            float* slot = sSCR + h4 * GSTRIDE + etid * 4;
            float4 ab = *(const float4*)slot;
            float4 wd = ((const float4*)sW1d)[h4];
            float4 b1 = ((const float4*)sB1)[h4];
            float pre[4], out[4];
            pre[0] = ab.x + dist * wd.x + b1.x;
            pre[1] = ab.y + dist * wd.y + b1.y;
            pre[2] = ab.z + dist * wd.z + b1.z;
            pre[3] = ab.w + dist * wd.w + b1.w;
#pragma unroll
            for (int kk = 0; kk < 4; ++kk) {
                int h = h4 * 4 + kk;
                const ulonglong2* wt = (const ulonglong2*)(sWee1t + h * EFD);
                ulonglong2 wA = wt[0], wB = wt[1];
                u64p acc2 = 0ULL;
                ffma2(acc2, epk[0], wA.x); ffma2(acc2, epk[1], wA.y);
                ffma2(acc2, epk[2], wB.x); ffma2(acc2, epk[3], wB.y);
                ulonglong2 wC = wt[2], wD = wt[3];
                ffma2(acc2, epk[4], wC.x); ffma2(acc2, epk[5], wC.y);
                ffma2(acc2, epk[6], wD.x); ffma2(acc2, epk[7], wD.y);
                float lo, hi; unpack2(acc2, lo, hi);
                out[kk] = siluf(pre[kk] + lo + hi);
            }
            *(float4*)slot = make_float4(out[0], out[1], out[2], out[3]);
        }
    }
    __syncthreads();

    // ---------------- Phase B: packed GEMM, tile 4e x 8c (strided edges) ----------------
    int et = tid & 31;   // edges et, et+32, et+64, et+96
    int ct = tid >> 5;   // channels [ct*8, ct*8+8)

    u64p acc[4][4];
    {
        const ulonglong2* b2p = (const ulonglong2*)(sB2 + ct * 8);
        ulonglong2 bA = b2p[0], bB = b2p[1];
#pragma unroll
        for (int ee = 0; ee < 4; ++ee) {
            acc[ee][0] = bA.x; acc[ee][1] = bA.y;
            acc[ee][2] = bB.x; acc[ee][3] = bB.y;
        }
    }

    const float* wbase = sWe2 + ct * 8;
#pragma unroll 4
    for (int h4 = 0; h4 < 16; ++h4) {
        const float* gbase = sSCR + h4 * GSTRIDE + et * 4;
        float4 f0 = *(const float4*)(gbase);            // edge et
        float4 f1 = *(const float4*)(gbase + 128);      // edge et+32
        float4 f2 = *(const float4*)(gbase + 256);      // edge et+64
        float4 f3 = *(const float4*)(gbase + 384);      // edge et+96
        float e0[4] = { f0.x, f0.y, f0.z, f0.w };
        float e1[4] = { f1.x, f1.y, f1.z, f1.w };
        float e2[4] = { f2.x, f2.y, f2.z, f2.w };
        float e3[4] = { f3.x, f3.y, f3.z, f3.w };
#pragma unroll
        for (int j = 0; j < 4; ++j) {
            const ulonglong2* w = (const ulonglong2*)(wbase + (h4 * 4 + j) * F);
            ulonglong2 wA = w[0], wB = w[1];
            u64p h0 = pack2(e0[j], e0[j]);
            u64p h1 = pack2(e1[j], e1[j]);
            u64p h2 = pack2(e2[j], e2[j]);
            u64p h3 = pack2(e3[j], e3[j]);
            ffma2(acc[0][0], h0, wA.x); ffma2(acc[0][1], h0, wA.y);
            ffma2(acc[0][2], h0, wB.x); ffma2(acc[0][3], h0, wB.y);
            ffma2(acc[1][0], h1, wA.x); ffma2(acc[1][1], h1, wA.y);
            ffma2(acc[1][2], h1, wB.x); ffma2(acc[1][3], h1, wB.y);
            ffma2(acc[2][0], h2, wA.x); ffma2(acc[2][1], h2, wA.y);
            ffma2(acc[2][2], h2, wB.x); ffma2(acc[2][3], h2, wB.y);
            ffma2(acc[3][0], h3, wA.x); ffma2(acc[3][1], h3, wA.y);
            ffma2(acc[3][2], h3, wB.x); ffma2(acc[3][3], h3, wB.y);
        }
    }
    __syncthreads();   // all Phase-B reads of SCR done before epilogue overwrites

    // ---- epilogue: silu*att into SCR as [c4][e][4] ----
#pragma unroll
    for (int ee = 0; ee < 4; ++ee) {
        int el = et + ee * 32;
        float att = sAtt[el];
#pragma unroll
        for (int q = 0; q < 2; ++q) {
            float v0, v1, v2, v3;
            unpack2(acc[ee][2 * q],     v0, v1);
            unpack2(acc[ee][2 * q + 1], v2, v3);
            *(float4*)(sSCR + (ct * 2 + q) * GSTRIDE + el * 4) =
                make_float4(siluf(v0) * att, siluf(v1) * att,
                            siluf(v2) * att, siluf(v3) * att);
        }
    }
    __syncthreads();

    // ---- coalesced REDG scatter ----
#pragma unroll
    for (int it = 0; it < 8; ++it) {
        int item = it * 256 + tid;   // 0..2047
        int e = item >> 4;
        int c = item & 15;
        float4 v = *(const float4*)(sSCR + c * GSTRIDE + e * 4);
        redAdd4(g_hneigh + (size_t)sDstA[e] * F + c * 4, v.x, v.y, v.z, v.w);
    }
}

// ================= K4: node MLP =================
__global__ void k4_node(const float* __restrict__ nf,
                        const float* __restrict__ Wn1,
                        const float* __restrict__ bn1,
                        const float* __restrict__ Wn2,
                        const float* __restrict__ bn2,
                        float* __restrict__ out) {
    __shared__ __align__(16) float sh1[4 * F];
    int tid = threadIdx.x;
    int ln = tid >> 6, c = tid & 63;
    int node = blockIdx.x * 4 + ln;

    const float4* nfr = (const float4*)(nf + (size_t)node * F);
    const float4* hr  = (const float4*)(g_hneigh + (size_t)node * F);

    float acc = bn1[c];
#pragma unroll 4
    for (int k4 = 0; k4 < 16; ++k4) {
        float4 x = __ldg(nfr + k4);
        acc += x.x * __ldg(Wn1 + (k4 * 4 + 0) * F + c);
        acc += x.y * __ldg(Wn1 + (k4 * 4 + 1) * F + c);
        acc += x.z * __ldg(Wn1 + (k4 * 4 + 2) * F + c);
        acc += x.w * __ldg(Wn1 + (k4 * 4 + 3) * F + c);
    }
#pragma unroll 4
    for (int k4 = 0; k4 < 16; ++k4) {
        float4 x = hr[k4];
        acc += x.x * __ldg(Wn1 + (F + k4 * 4 + 0) * F + c);
        acc += x.y * __ldg(Wn1 + (F + k4 * 4 + 1) * F + c);
        acc += x.z * __ldg(Wn1 + (F + k4 * 4 + 2) * F + c);
        acc += x.w * __ldg(Wn1 + (F + k4 * 4 + 3) * F + c);
    }
    sh1[ln * F + c] = siluf(acc);
    __syncthreads();

    const float* h1r = sh1 + ln * F;
    float o = bn2[c];
#pragma unroll 4
    for (int k4 = 0; k4 < 16; ++k4) {
        o += h1r[k4 * 4 + 0] * __ldg(Wn2 + (k4 * 4 + 0) * F + c);
        o += h1r[k4 * 4 + 1] * __ldg(Wn2 + (k4 * 4 + 1) * F + c);
        o += h1r[k4 * 4 + 2] * __ldg(Wn2 + (k4 * 4 + 2) * F + c);
        o += h1r[k4 * 4 + 3] * __ldg(Wn2 + (k4 * 4 + 3) * F + c);
    }
    out[(size_t)node * F + c] = o;
}

extern "C" void kernel_launch(void* const* d_in, const int* in_sizes, int n_in,
                              void* d_out, int out_size) {
    const float* nf    = (const float*)d_in[0];
    const float* coord = (const float*)d_in[1];
    const float* efeat = (const float*)d_in[2];
    const float* We1   = (const float*)d_in[3];
    const float* be1   = (const float*)d_in[4];
    const float* We2   = (const float*)d_in[5];
    const float* be2   = (const float*)d_in[6];
    const float* Wn1   = (const float*)d_in[7];
    const float* bn1   = (const float*)d_in[8];
    const float* Wn2   = (const float*)d_in[9];
    const float* bn2   = (const float*)d_in[10];
    const float* Wq    = (const float*)d_in[11];
    const float* Wk    = (const float*)d_in[12];
    const int*   src   = (const int*)d_in[13];
    const int*   dst   = (const int*)d_in[14];
    float* out = (float*)d_out;

    const int k3_smem = SM_FLOATS * (int)sizeof(float);
    cudaFuncSetAttribute(k3_message, cudaFuncAttributeMaxDynamicSharedMemorySize, k3_smem);

    k0_node_pre<<<NN / 4, 256>>>(nf, We1, Wk, Wq);
    k1_scores<<<EE / 128, 256>>>(coord, efeat, src, dst);
    k3_message<<<EE / EPB, 256, k3_smem>>>(efeat, We1, be1, We2, be2, src, dst);
    k4_node<<<NN / 4, 256>>>(nf, Wn1, bn1, Wn2, bn2, out);
}

// round 10
// speedup vs baseline: 1.0782x; 1.0100x over previous
#include <cuda_runtime.h>
#include <math.h>

#define NN 10000
#define EE 640000
#define F  64
#define EFD 16

typedef unsigned long long u64p;

// ---- scratch (device globals; no allocations allowed) ----
__device__ float g_Asrc[NN*F];
__device__ float g_Adst[NN*F];
__device__ float g_Kn[NN*F];
__device__ float g_Qn[NN*F];
__device__ float g_Qk[NN*EFD];
__device__ float g_qd2[NN];
__device__ float g_denom[NN];
__device__ float g_hneigh[NN*F];
__device__ float g_e[EE];      // holds exp(score) after K1
__device__ float g_dist[EE];

__device__ __forceinline__ float siluf(float x) { return x / (1.f + __expf(-x)); }

__device__ __forceinline__ void redAdd4(float* addr, float a, float b, float c, float d) {
    asm volatile("red.global.add.v4.f32 [%0], {%1,%2,%3,%4};"
                 :: "l"(addr), "f"(a), "f"(b), "f"(c), "f"(d) : "memory");
}

__device__ __forceinline__ u64p pack2(float x, float y) {
    u64p r; asm("mov.b64 %0, {%1,%2};" : "=l"(r) : "f"(x), "f"(y)); return r;
}
__device__ __forceinline__ void unpack2(u64p v, float& x, float& y) {
    asm("mov.b64 {%0,%1}, %2;" : "=f"(x), "=f"(y) : "l"(v));
}
__device__ __forceinline__ void ffma2(u64p& d, u64p a, u64p b) {
    asm("fma.rn.f32x2 %0, %1, %2, %0;" : "+l"(d) : "l"(a), "l"(b));
}

// ================= K0: per-node precompute + init =================
__global__ void k0_node_pre(const float* __restrict__ nf,
                            const float* __restrict__ We1,
                            const float* __restrict__ Wk,
                            const float* __restrict__ Wq) {
    __shared__ __align__(16) float srow[4 * F];
    __shared__ __align__(16) float sQ[4 * F];
    int tid = threadIdx.x;
    int nodeBase = blockIdx.x * 4;
    srow[tid] = nf[(size_t)nodeBase * F + tid];
    __syncthreads();
    int ln = tid >> 6;
    int c  = tid & 63;
    int node = nodeBase + ln;
    const float* r = srow + ln * F;
    float a0 = 0.f, a1 = 0.f, a2 = 0.f, a3 = 0.f;
#pragma unroll 8
    for (int k = 0; k < F; ++k) {
        float x = r[k];
        a0 += x * __ldg(We1 + k * F + c);
        a1 += x * __ldg(We1 + (F + k) * F + c);
        a2 += x * __ldg(Wk  + k * F + c);
        a3 += x * __ldg(Wq  + k * F + c);
    }
    g_Asrc[node * F + c] = a0;
    g_Adst[node * F + c] = a1;
    g_Kn  [node * F + c] = a2;
    g_Qn  [node * F + c] = a3;
    sQ[ln * F + c] = a3;
    g_hneigh[node * F + c] = 0.f;
    if (c == 0) g_denom[node] = 0.f;
    __syncthreads();
    if (tid < 64) {
        int ln2 = tid >> 4, j = tid & 15;
        const float* q = sQ + ln2 * F;
        float acc = 0.f;
#pragma unroll 8
        for (int k = 0; k < F; ++k) acc += q[k] * __ldg(Wk + (65 + j) * F + k);
        g_Qk[(nodeBase + ln2) * EFD + j] = acc;
    } else if (tid < 68) {
        int ln2 = tid - 64;
        const float* q = sQ + ln2 * F;
        float acc = 0.f;
#pragma unroll 8
        for (int k = 0; k < F; ++k) acc += q[k] * __ldg(Wk + 64 * F + k);
        g_qd2[nodeBase + ln2] = acc;
    }
}

// ================= K1: edge scores -> exp(e), denom atomicAdd =================
__global__ void __launch_bounds__(256)
k1_scores(const float* __restrict__ coord,
          const float* __restrict__ efeat,
          const int* __restrict__ src,
          const int* __restrict__ dst) {
    int tid = threadIdx.x;
    int warp = tid >> 5, lane = tid & 31;
    int sub = lane >> 4, c = lane & 15;
    int base = blockIdx.x * 128 + warp * 16;

#pragma unroll
    for (int it = 0; it < 8; ++it) {
        int e = base + it * 2 + sub;
        int s = __ldg(&src[e]);
        int d = __ldg(&dst[e]);

        float4 kv = __ldg((const float4*)(g_Kn + (size_t)s * F) + c);
        float4 qv = __ldg((const float4*)(g_Qn + (size_t)d * F) + c);
        float part = kv.x * qv.x + kv.y * qv.y + kv.z * qv.z + kv.w * qv.w;

        if (c < 4) {
            float4 ev = __ldg((const float4*)(efeat + (size_t)e * EFD) + c);
            float4 qk = __ldg((const float4*)(g_Qk + (size_t)d * EFD) + c);
            part += ev.x * qk.x + ev.y * qk.y + ev.z * qk.z + ev.w * qk.w;
        }

        float dist = 0.f;
        if (c == 0) {
            float dx = __ldg(&coord[s * 3 + 0]) - __ldg(&coord[d * 3 + 0]);
            float dy = __ldg(&coord[s * 3 + 1]) - __ldg(&coord[d * 3 + 1]);
            float dz = __ldg(&coord[s * 3 + 2]) - __ldg(&coord[d * 3 + 2]);
            dist = sqrtf(dx * dx + dy * dy + dz * dz);
            part += dist * __ldg(&g_qd2[d]);
        }

#pragma unroll
        for (int o = 8; o; o >>= 1)
            part += __shfl_down_sync(0xffffffffu, part, o, 16);

        if (c == 0) {
            float v = __expf(part * 0.125f);
            g_e[e] = v;
            g_dist[e] = dist;
            atomicAdd(&g_denom[d], v);
        }
    }
}

// ================= K3: dual-GEMM edge message + scatter =================
// Block = 256 threads, 128 edges, 50.9KB smem -> 4 blocks/SM.
// SCR union [16 groups][stride 516]:
//  - gather writes Asrc[s]+Adst[d] as [h4][e][4]
//  - Phase A (GEMM K=17 over [dist, ef]): h1 = silu(pre + b1 + Wa^T@efx), in place
//  - X region: [efT 17x132 | Wa 17x64] during A, then re-staged as We2 for B
//  - Phase B GEMM tile 4e x 8c (strided edges) -> epilogue [c4][e][4] -> REDG scatter
#define EPB 128
#define GSTRIDE 516
#define EFTS 132
#define SM_SCR   0            // 16*516 = 8256
#define SM_X     8256         // 4096 (efT@0 [2244], Wa@2244 [1088]) -> We2 in Phase B
#define SM_B1    12352        // 64
#define SM_B2    12416        // 64
#define SM_ATT   12480        // 128
#define SM_DSTI  12608        // 128 ints
#define SM_FLOATS 12736

__global__ void __launch_bounds__(256, 4)
k3_message(const float* __restrict__ efeat,
           const float* __restrict__ We1,
           const float* __restrict__ be1,
           const float* __restrict__ We2,
           const float* __restrict__ be2,
           const int* __restrict__ src,
           const int* __restrict__ dst) {
    extern __shared__ __align__(16) float sm[];
    float* sSCR  = sm + SM_SCR;
    float* sX    = sm + SM_X;          // efT | Wa, later We2
    float* sEfT  = sX;                 // [17][EFTS]
    float* sWa   = sX + 17 * EFTS;     // [17][64]
    float* sB1   = sm + SM_B1;
    float* sB2   = sm + SM_B2;
    float* sAtt  = sm + SM_ATT;
    int*   sDstA = (int*)(sm + SM_DSTI);

    int tid = threadIdx.x;
    int blockbase = blockIdx.x * EPB;

    // ---- stage Wa (rows: 0=dist row We1[128], 1..16 = We1[129+j]) ----
    for (int i = tid; i < 17 * F; i += 256) sWa[i] = We1[128 * F + i];
    if (tid >= 192) {
        int t = tid - 192;   // 0..63
        sB1[t] = be1[t];
        sB2[t] = be2[t];
    }
    // ---- per-edge scalars: dst, att, dist (dist goes to efT row 0) ----
    if (tid < 128) {
        int e = blockbase + tid;
        int d = __ldg(&dst[e]);
        sDstA[tid] = d;
        sAtt[tid] = __fdividef(__ldg(&g_e[e]), __ldg(&g_denom[d]));
        sEfT[tid] = __ldg(&g_dist[e]);   // row 0 = dist
    }
    // ---- stage efeat transposed into efT rows 1..16 ----
#pragma unroll
    for (int it = 0; it < 2; ++it) {
        int item = it * 256 + tid;   // 0..511
        int e = item >> 2;
        int c = item & 3;
        float4 v = __ldg((const float4*)(efeat + (size_t)(blockbase + e) * EFD) + c);
        sEfT[(c * 4 + 1) * EFTS + e] = v.x;
        sEfT[(c * 4 + 2) * EFTS + e] = v.y;
        sEfT[(c * 4 + 3) * EFTS + e] = v.z;
        sEfT[(c * 4 + 4) * EFTS + e] = v.w;
    }
    // ---- coalesced gather of Asrc[s]+Adst[d] into [h4][e][4] ----
#pragma unroll
    for (int it = 0; it < 8; ++it) {
        int item = it * 256 + tid;   // 0..2047
        int e = item >> 4;
        int c = item & 15;           // h4 group
        int s = __ldg(&src[blockbase + e]);
        int d = __ldg(&dst[blockbase + e]);
        float4 a = __ldg((const float4*)(g_Asrc + (size_t)s * F) + c);
        float4 b = __ldg((const float4*)(g_Adst + (size_t)d * F) + c);
        *(float4*)(sSCR + c * GSTRIDE + e * 4) =
            make_float4(a.x + b.x, a.y + b.y, a.z + b.z, a.w + b.w);
    }
    __syncthreads();

    // ---------------- Phase A: GEMM K=17, tile 4 consecutive edges x 8 h ----------------
    {
        int ea = (tid & 31) * 4;     // edges ea..ea+3
        int ht = tid >> 5;           // h = ht*8 .. ht*8+7

        u64p a[4][4];                // [edge][hpair]
        {
            const ulonglong2* b1p = (const ulonglong2*)(sB1 + ht * 8);
            ulonglong2 bA = b1p[0], bB = b1p[1];
#pragma unroll
            for (int e = 0; e < 4; ++e) {
                a[e][0] = bA.x; a[e][1] = bA.y;
                a[e][2] = bB.x; a[e][3] = bB.y;
            }
        }

#pragma unroll
        for (int j = 0; j < 17; ++j) {
            float4 ef4 = *(const float4*)(sEfT + j * EFTS + ea);
            const ulonglong2* wp = (const ulonglong2*)(sWa + j * F + ht * 8);
            ulonglong2 wA = wp[0], wB = wp[1];
            u64p p0 = pack2(ef4.x, ef4.x);
            u64p p1 = pack2(ef4.y, ef4.y);
            u64p p2 = pack2(ef4.z, ef4.z);
            u64p p3 = pack2(ef4.w, ef4.w);
            ffma2(a[0][0], p0, wA.x); ffma2(a[0][1], p0, wA.y);
            ffma2(a[0][2], p0, wB.x); ffma2(a[0][3], p0, wB.y);
            ffma2(a[1][0], p1, wA.x); ffma2(a[1][1], p1, wA.y);
            ffma2(a[1][2], p1, wB.x); ffma2(a[1][3], p1, wB.y);
            ffma2(a[2][0], p2, wA.x); ffma2(a[2][1], p2, wA.y);
            ffma2(a[2][2], p2, wB.x); ffma2(a[2][3], p2, wB.y);
            ffma2(a[3][0], p3, wA.x); ffma2(a[3][1], p3, wA.y);
            ffma2(a[3][2], p3, wB.x); ffma2(a[3][3], p3, wB.y);
        }

        // silu(pre + acc) in place
#pragma unroll
        for (int e = 0; e < 4; ++e) {
            int el = ea + e;
#pragma unroll
            for (int g = 0; g < 2; ++g) {
                float* slot = sSCR + (2 * ht + g) * GSTRIDE + el * 4;
                float4 pre = *(const float4*)slot;
                float a0, a1, a2, a3;
                unpack2(a[e][2 * g],     a0, a1);
                unpack2(a[e][2 * g + 1], a2, a3);
                *(float4*)slot = make_float4(siluf(pre.x + a0), siluf(pre.y + a1),
                                             siluf(pre.z + a2), siluf(pre.w + a3));
            }
        }
    }
    __syncthreads();

    // ---- re-stage X as We2 ----
    for (int i = tid; i < F * F; i += 256) sX[i] = We2[i];
    __syncthreads();

    // ---------------- Phase B: packed GEMM, tile 4e x 8c (strided edges) ----------------
    int et = tid & 31;   // edges et, et+32, et+64, et+96
    int ct = tid >> 5;   // channels [ct*8, ct*8+8)

    u64p acc[4][4];
    {
        const ulonglong2* b2p = (const ulonglong2*)(sB2 + ct * 8);
        ulonglong2 bA = b2p[0], bB = b2p[1];
#pragma unroll
        for (int ee = 0; ee < 4; ++ee) {
            acc[ee][0] = bA.x; acc[ee][1] = bA.y;
            acc[ee][2] = bB.x; acc[ee][3] = bB.y;
        }
    }

    const float* wbase = sX + ct * 8;
#pragma unroll 4
    for (int h4 = 0; h4 < 16; ++h4) {
        const float* gbase = sSCR + h4 * GSTRIDE + et * 4;
        float4 f0 = *(const float4*)(gbase);            // edge et
        float4 f1 = *(const float4*)(gbase + 128);      // edge et+32
        float4 f2 = *(const float4*)(gbase + 256);      // edge et+64
        float4 f3 = *(const float4*)(gbase + 384);      // edge et+96
        float e0[4] = { f0.x, f0.y, f0.z, f0.w };
        float e1[4] = { f1.x, f1.y, f1.z, f1.w };
        float e2[4] = { f2.x, f2.y, f2.z, f2.w };
        float e3[4] = { f3.x, f3.y, f3.z, f3.w };
#pragma unroll
        for (int j = 0; j < 4; ++j) {
            const ulonglong2* w = (const ulonglong2*)(wbase + (h4 * 4 + j) * F);
            ulonglong2 wA = w[0], wB = w[1];
            u64p h0 = pack2(e0[j], e0[j]);
            u64p h1 = pack2(e1[j], e1[j]);
            u64p h2 = pack2(e2[j], e2[j]);
            u64p h3 = pack2(e3[j], e3[j]);
            ffma2(acc[0][0], h0, wA.x); ffma2(acc[0][1], h0, wA.y);
            ffma2(acc[0][2], h0, wB.x); ffma2(acc[0][3], h0, wB.y);
            ffma2(acc[1][0], h1, wA.x); ffma2(acc[1][1], h1, wA.y);
            ffma2(acc[1][2], h1, wB.x); ffma2(acc[1][3], h1, wB.y);
            ffma2(acc[2][0], h2, wA.x); ffma2(acc[2][1], h2, wA.y);
            ffma2(acc[2][2], h2, wB.x); ffma2(acc[2][3], h2, wB.y);
            ffma2(acc[3][0], h3, wA.x); ffma2(acc[3][1], h3, wA.y);
            ffma2(acc[3][2], h3, wB.x); ffma2(acc[3][3], h3, wB.y);
        }
    }
    __syncthreads();   // all Phase-B reads of SCR done before epilogue overwrites

    // ---- epilogue: silu*att into SCR as [c4][e][4] ----
#pragma unroll
    for (int ee = 0; ee < 4; ++ee) {
        int el = et + ee * 32;
        float att = sAtt[el];
#pragma unroll
        for (int q = 0; q < 2; ++q) {
            float v0, v1, v2, v3;
            unpack2(acc[ee][2 * q],     v0, v1);
            unpack2(acc[ee][2 * q + 1], v2, v3);
            *(float4*)(sSCR + (ct * 2 + q) * GSTRIDE + el * 4) =
                make_float4(siluf(v0) * att, siluf(v1) * att,
                            siluf(v2) * att, siluf(v3) * att);
        }
    }
    __syncthreads();

    // ---- coalesced REDG scatter ----
#pragma unroll
    for (int it = 0; it < 8; ++it) {
        int item = it * 256 + tid;   // 0..2047
        int e = item >> 4;
        int c = item & 15;
        float4 v = *(const float4*)(sSCR + c * GSTRIDE + e * 4);
        redAdd4(g_hneigh + (size_t)sDstA[e] * F + c * 4, v.x, v.y, v.z, v.w);
    }
}

// ================= K4: node MLP =================
__global__ void k4_node(const float* __restrict__ nf,
                        const float* __restrict__ Wn1,
                        const float* __restrict__ bn1,
                        const float* __restrict__ Wn2,
                        const float* __restrict__ bn2,
                        float* __restrict__ out) {
    __shared__ __align__(16) float sh1[4 * F];
    int tid = threadIdx.x;
    int ln = tid >> 6, c = tid & 63;
    int node = blockIdx.x * 4 + ln;

    const float4* nfr = (const float4*)(nf + (size_t)node * F);
    const float4* hr  = (const float4*)(g_hneigh + (size_t)node * F);

    float acc = bn1[c];
#pragma unroll 4
    for (int k4 = 0; k4 < 16; ++k4) {
        float4 x = __ldg(nfr + k4);
        acc += x.x * __ldg(Wn1 + (k4 * 4 + 0) * F + c);
        acc += x.y * __ldg(Wn1 + (k4 * 4 + 1) * F + c);
        acc += x.z * __ldg(Wn1 + (k4 * 4 + 2) * F + c);
        acc += x.w * __ldg(Wn1 + (k4 * 4 + 3) * F + c);
    }
#pragma unroll 4
    for (int k4 = 0; k4 < 16; ++k4) {
        float4 x = hr[k4];
        acc += x.x * __ldg(Wn1 + (F + k4 * 4 + 0) * F + c);
        acc += x.y * __ldg(Wn1 + (F + k4 * 4 + 1) * F + c);
        acc += x.z * __ldg(Wn1 + (F + k4 * 4 + 2) * F + c);
        acc += x.w * __ldg(Wn1 + (F + k4 * 4 + 3) * F + c);
    }
    sh1[ln * F + c] = siluf(acc);
    __syncthreads();

    const float* h1r = sh1 + ln * F;
    float o = bn2[c];
#pragma unroll 4
    for (int k4 = 0; k4 < 16; ++k4) {
        o += h1r[k4 * 4 + 0] * __ldg(Wn2 + (k4 * 4 + 0) * F + c);
        o += h1r[k4 * 4 + 1] * __ldg(Wn2 + (k4 * 4 + 1) * F + c);
        o += h1r[k4 * 4 + 2] * __ldg(Wn2 + (k4 * 4 + 2) * F + c);
        o += h1r[k4 * 4 + 3] * __ldg(Wn2 + (k4 * 4 + 3) * F + c);
    }
    out[(size_t)node * F + c] = o;
}

extern "C" void kernel_launch(void* const* d_in, const int* in_sizes, int n_in,
                              void* d_out, int out_size) {
    const float* nf    = (const float*)d_in[0];
    const float* coord = (const float*)d_in[1];
    const float* efeat = (const float*)d_in[2];
    const float* We1   = (const float*)d_in[3];
    const float* be1   = (const float*)d_in[4];
    const float* We2   = (const float*)d_in[5];
    const float* be2   = (const float*)d_in[6];
    const float* Wn1   = (const float*)d_in[7];
    const float* bn1   = (const float*)d_in[8];
    const float* Wn2   = (const float*)d_in[9];
    const float* bn2   = (const float*)d_in[10];
    const float* Wq    = (const float*)d_in[11];
    const float* Wk    = (const float*)d_in[12];
    const int*   src   = (const int*)d_in[13];
    const int*   dst   = (const int*)d_in[14];
    float* out = (float*)d_out;

    const int k3_smem = SM_FLOATS * (int)sizeof(float);
    cudaFuncSetAttribute(k3_message, cudaFuncAttributeMaxDynamicSharedMemorySize, k3_smem);

    k0_node_pre<<<NN / 4, 256>>>(nf, We1, Wk, Wq);
    k1_scores<<<EE / 128, 256>>>(coord, efeat, src, dst);
    k3_message<<<EE / EPB, 256, k3_smem>>>(efeat, We1, be1, We2, be2, src, dst);
    k4_node<<<NN / 4, 256>>>(nf, Wn1, bn1, Wn2, bn2, out);
}

// round 13
// speedup vs baseline: 1.1026x; 1.0226x over previous
#include <cuda_runtime.h>
#include <stdint.h>
#include <math.h>

#define NN 10000
#define EE 640000
#define F  64
#define EFD 16

typedef unsigned long long u64p;

// ---- scratch (device globals; no allocations allowed) ----
__device__ float g_Asrc[NN*F];
__device__ float g_Adst[NN*F];
__device__ float g_Kn[NN*F];
__device__ float g_Qn[NN*F];
__device__ float g_Qk[NN*EFD];
__device__ float g_qd2[NN];
__device__ float g_denom[NN];
__device__ float g_hneigh[NN*F];
__device__ float g_e[EE];      // holds exp(score) after K1
__device__ float g_dist[EE];

__device__ __forceinline__ float siluf(float x) { return x / (1.f + __expf(-x)); }

__device__ __forceinline__ void redAdd4(float* addr, float a, float b, float c, float d) {
    asm volatile("red.global.add.v4.f32 [%0], {%1,%2,%3,%4};"
                 :: "l"(addr), "f"(a), "f"(b), "f"(c), "f"(d) : "memory");
}

__device__ __forceinline__ u64p pack2(float x, float y) {
    u64p r; asm("mov.b64 %0, {%1,%2};" : "=l"(r) : "f"(x), "f"(y)); return r;
}
__device__ __forceinline__ void unpack2(u64p v, float& x, float& y) {
    asm("mov.b64 {%0,%1}, %2;" : "=f"(x), "=f"(y) : "l"(v));
}
__device__ __forceinline__ void ffma2(u64p& d, u64p a, u64p b) {
    asm("fma.rn.f32x2 %0, %1, %2, %0;" : "+l"(d) : "l"(a), "l"(b));
}

// ================= K0: per-node precompute + init =================
__global__ void k0_node_pre(const float* __restrict__ nf,
                            const float* __restrict__ We1,
                            const float* __restrict__ Wk,
                            const float* __restrict__ Wq) {
    __shared__ __align__(16) float srow[4 * F];
    __shared__ __align__(16) float sQ[4 * F];
    int tid = threadIdx.x;
    int nodeBase = blockIdx.x * 4;
    srow[tid] = nf[(size_t)nodeBase * F + tid];
    __syncthreads();
    int ln = tid >> 6;
    int c  = tid & 63;
    int node = nodeBase + ln;
    const float* r = srow + ln * F;
    float a0 = 0.f, a1 = 0.f, a2 = 0.f, a3 = 0.f;
#pragma unroll 8
    for (int k = 0; k < F; ++k) {
        float x = r[k];
        a0 += x * __ldg(We1 + k * F + c);
        a1 += x * __ldg(We1 + (F + k) * F + c);
        a2 += x * __ldg(Wk  + k * F + c);
        a3 += x * __ldg(Wq  + k * F + c);
    }
    g_Asrc[node * F + c] = a0;
    g_Adst[node * F + c] = a1;
    g_Kn  [node * F + c] = a2;
    g_Qn  [node * F + c] = a3;
    sQ[ln * F + c] = a3;
    g_hneigh[node * F + c] = 0.f;
    if (c == 0) g_denom[node] = 0.f;
    __syncthreads();
    if (tid < 64) {
        int ln2 = tid >> 4, j = tid & 15;
        const float* q = sQ + ln2 * F;
        float acc = 0.f;
#pragma unroll 8
        for (int k = 0; k < F; ++k) acc += q[k] * __ldg(Wk + (65 + j) * F + k);
        g_Qk[(nodeBase + ln2) * EFD + j] = acc;
    } else if (tid < 68) {
        int ln2 = tid - 64;
        const float* q = sQ + ln2 * F;
        float acc = 0.f;
#pragma unroll 8
        for (int k = 0; k < F; ++k) acc += q[k] * __ldg(Wk + 64 * F + k);
        g_qd2[nodeBase + ln2] = acc;
    }
}

// ================= K1: edge scores -> exp(e), denom atomicAdd =================
__global__ void __launch_bounds__(256)
k1_scores(const float* __restrict__ coord,
          const float* __restrict__ efeat,
          const int* __restrict__ src,
          const int* __restrict__ dst) {
    int tid = threadIdx.x;
    int warp = tid >> 5, lane = tid & 31;
    int sub = lane >> 4, c = lane & 15;
    int base = blockIdx.x * 128 + warp * 16;

#pragma unroll
    for (int it = 0; it < 8; ++it) {
        int e = base + it * 2 + sub;
        int s = __ldg(&src[e]);
        int d = __ldg(&dst[e]);

        float4 kv = __ldg((const float4*)(g_Kn + (size_t)s * F) + c);
        float4 qv = __ldg((const float4*)(g_Qn + (size_t)d * F) + c);
        float part = kv.x * qv.x + kv.y * qv.y + kv.z * qv.z + kv.w * qv.w;

        if (c < 4) {
            float4 ev = __ldg((const float4*)(efeat + (size_t)e * EFD) + c);
            float4 qk = __ldg((const float4*)(g_Qk + (size_t)d * EFD) + c);
            part += ev.x * qk.x + ev.y * qk.y + ev.z * qk.z + ev.w * qk.w;
        }

        float dist = 0.f;
        if (c == 0) {
            float dx = __ldg(&coord[s * 3 + 0]) - __ldg(&coord[d * 3 + 0]);
            float dy = __ldg(&coord[s * 3 + 1]) - __ldg(&coord[d * 3 + 1]);
            float dz = __ldg(&coord[s * 3 + 2]) - __ldg(&coord[d * 3 + 2]);
            dist = sqrtf(dx * dx + dy * dy + dz * dz);
            part += dist * __ldg(&g_qd2[d]);
        }

#pragma unroll
        for (int o = 8; o; o >>= 1)
            part += __shfl_down_sync(0xffffffffu, part, o, 16);

        if (c == 0) {
            float v = __expf(part * 0.125f);
            g_e[e] = v;
            g_dist[e] = dist;
            atomicAdd(&g_denom[d], v);
        }
    }
}

// ================= K3: dual-GEMM edge message + scatter (R10 base) =================
#define EPB 128
#define GSTRIDE 516
#define EFTS 132
#define SM_SCR   0            // 16*516 = 8256
#define SM_X     8256         // 4096 (efT@0 [2244], Wa@2244 [1088]) -> We2 in Phase B
#define SM_B1    12352        // 64
#define SM_B2    12416        // 64
#define SM_ATT   12480        // 128
#define SM_DSTI  12608        // 128 ints
#define SM_FLOATS 12736

__global__ void __launch_bounds__(256, 4)
k3_message(const float* __restrict__ efeat,
           const float* __restrict__ We1,
           const float* __restrict__ be1,
           const float* __restrict__ We2,
           const float* __restrict__ be2,
           const int* __restrict__ src,
           const int* __restrict__ dst) {
    extern __shared__ __align__(16) float sm[];
    float* sSCR  = sm + SM_SCR;
    float* sX    = sm + SM_X;          // efT | Wa, later We2
    float* sEfT  = sX;                 // [17][EFTS]
    float* sWa   = sX + 17 * EFTS;     // [17][64]
    float* sB1   = sm + SM_B1;
    float* sB2   = sm + SM_B2;
    float* sAtt  = sm + SM_ATT;
    int*   sDstA = (int*)(sm + SM_DSTI);

    int tid = threadIdx.x;
    int blockbase = blockIdx.x * EPB;

    // ---- stage Wa (rows: 0=dist row We1[128], 1..16 = We1[129+j]) ----
    for (int i = tid; i < 17 * F; i += 256) sWa[i] = We1[128 * F + i];
    if (tid >= 192) {
        int t = tid - 192;   // 0..63
        sB1[t] = be1[t];
        sB2[t] = be2[t];
    }
    // ---- per-edge scalars ----
    if (tid < 128) {
        int e = blockbase + tid;
        int d = __ldg(&dst[e]);
        sDstA[tid] = d;
        sAtt[tid] = __fdividef(__ldg(&g_e[e]), __ldg(&g_denom[d]));
        sEfT[tid] = __ldg(&g_dist[e]);   // row 0 = dist
    }
    // ---- stage efeat transposed into efT rows 1..16 ----
#pragma unroll
    for (int it = 0; it < 2; ++it) {
        int item = it * 256 + tid;   // 0..511
        int e = item >> 2;
        int c = item & 3;
        float4 v = __ldg((const float4*)(efeat + (size_t)(blockbase + e) * EFD) + c);
        sEfT[(c * 4 + 1) * EFTS + e] = v.x;
        sEfT[(c * 4 + 2) * EFTS + e] = v.y;
        sEfT[(c * 4 + 3) * EFTS + e] = v.z;
        sEfT[(c * 4 + 4) * EFTS + e] = v.w;
    }
    // ---- coalesced gather of Asrc[s]+Adst[d] into [h4][e][4] ----
#pragma unroll
    for (int it = 0; it < 8; ++it) {
        int item = it * 256 + tid;   // 0..2047
        int e = item >> 4;
        int c = item & 15;           // h4 group
        int s = __ldg(&src[blockbase + e]);
        int d = __ldg(&dst[blockbase + e]);
        float4 a = __ldg((const float4*)(g_Asrc + (size_t)s * F) + c);
        float4 b = __ldg((const float4*)(g_Adst + (size_t)d * F) + c);
        *(float4*)(sSCR + c * GSTRIDE + e * 4) =
            make_float4(a.x + b.x, a.y + b.y, a.z + b.z, a.w + b.w);
    }
    __syncthreads();

    // ---------------- Phase A: GEMM K=17, tile 4 consecutive edges x 8 h ----------------
    {
        int ea = (tid & 31) * 4;     // edges ea..ea+3
        int ht = tid >> 5;           // h = ht*8 .. ht*8+7

        u64p a[4][4];                // [edge][hpair]
        {
            const ulonglong2* b1p = (const ulonglong2*)(sB1 + ht * 8);
            ulonglong2 bA = b1p[0], bB = b1p[1];
#pragma unroll
            for (int e = 0; e < 4; ++e) {
                a[e][0] = bA.x; a[e][1] = bA.y;
                a[e][2] = bB.x; a[e][3] = bB.y;
            }
        }

#pragma unroll
        for (int j = 0; j < 17; ++j) {
            float4 ef4 = *(const float4*)(sEfT + j * EFTS + ea);
            const ulonglong2* wp = (const ulonglong2*)(sWa + j * F + ht * 8);
            ulonglong2 wA = wp[0], wB = wp[1];
            u64p p0 = pack2(ef4.x, ef4.x);
            u64p p1 = pack2(ef4.y, ef4.y);
            u64p p2 = pack2(ef4.z, ef4.z);
            u64p p3 = pack2(ef4.w, ef4.w);
            ffma2(a[0][0], p0, wA.x); ffma2(a[0][1], p0, wA.y);
            ffma2(a[0][2], p0, wB.x); ffma2(a[0][3], p0, wB.y);
            ffma2(a[1][0], p1, wA.x); ffma2(a[1][1], p1, wA.y);
            ffma2(a[1][2], p1, wB.x); ffma2(a[1][3], p1, wB.y);
            ffma2(a[2][0], p2, wA.x); ffma2(a[2][1], p2, wA.y);
            ffma2(a[2][2], p2, wB.x); ffma2(a[2][3], p2, wB.y);
            ffma2(a[3][0], p3, wA.x); ffma2(a[3][1], p3, wA.y);
            ffma2(a[3][2], p3, wB.x); ffma2(a[3][3], p3, wB.y);
        }

        // silu(pre + acc) in place
#pragma unroll
        for (int e = 0; e < 4; ++e) {
            int el = ea + e;
#pragma unroll
            for (int g = 0; g < 2; ++g) {
                float* slot = sSCR + (2 * ht + g) * GSTRIDE + el * 4;
                float4 pre = *(const float4*)slot;
                float a0, a1, a2, a3;
                unpack2(a[e][2 * g],     a0, a1);
                unpack2(a[e][2 * g + 1], a2, a3);
                *(float4*)slot = make_float4(siluf(pre.x + a0), siluf(pre.y + a1),
                                             siluf(pre.z + a2), siluf(pre.w + a3));
            }
        }
    }
    __syncthreads();

    // ---- re-stage X as We2 ----
    for (int i = tid; i < F * F; i += 256) sX[i] = We2[i];
    __syncthreads();

    // ---------------- Phase B: packed GEMM, tile 4e x 8c (strided edges) ----------------
    int et = tid & 31;   // edges et, et+32, et+64, et+96
    int ct = tid >> 5;   // channels [ct*8, ct*8+8)

    u64p acc[4][4];
    {
        const ulonglong2* b2p = (const ulonglong2*)(sB2 + ct * 8);
        ulonglong2 bA = b2p[0], bB = b2p[1];
#pragma unroll
        for (int ee = 0; ee < 4; ++ee) {
            acc[ee][0] = bA.x; acc[ee][1] = bA.y;
            acc[ee][2] = bB.x; acc[ee][3] = bB.y;
        }
    }

    const float* wbase = sX + ct * 8;
#pragma unroll 4
    for (int h4 = 0; h4 < 16; ++h4) {
        const float* gbase = sSCR + h4 * GSTRIDE + et * 4;
        float4 f0 = *(const float4*)(gbase);            // edge et
        float4 f1 = *(const float4*)(gbase + 128);      // edge et+32
        float4 f2 = *(const float4*)(gbase + 256);      // edge et+64
        float4 f3 = *(const float4*)(gbase + 384);      // edge et+96
        float e0[4] = { f0.x, f0.y, f0.z, f0.w };
        float e1[4] = { f1.x, f1.y, f1.z, f1.w };
        float e2[4] = { f2.x, f2.y, f2.z, f2.w };
        float e3[4] = { f3.x, f3.y, f3.z, f3.w };
#pragma unroll
        for (int j = 0; j < 4; ++j) {
            const ulonglong2* w = (const ulonglong2*)(wbase + (h4 * 4 + j) * F);
            ulonglong2 wA = w[0], wB = w[1];
            u64p h0 = pack2(e0[j], e0[j]);
            u64p h1 = pack2(e1[j], e1[j]);
            u64p h2 = pack2(e2[j], e2[j]);
            u64p h3 = pack2(e3[j], e3[j]);
            ffma2(acc[0][0], h0, wA.x); ffma2(acc[0][1], h0, wA.y);
            ffma2(acc[0][2], h0, wB.x); ffma2(acc[0][3], h0, wB.y);
            ffma2(acc[1][0], h1, wA.x); ffma2(acc[1][1], h1, wA.y);
            ffma2(acc[1][2], h1, wB.x); ffma2(acc[1][3], h1, wB.y);
            ffma2(acc[2][0], h2, wA.x); ffma2(acc[2][1], h2, wA.y);
            ffma2(acc[2][2], h2, wB.x); ffma2(acc[2][3], h2, wB.y);
            ffma2(acc[3][0], h3, wA.x); ffma2(acc[3][1], h3, wA.y);
            ffma2(acc[3][2], h3, wB.x); ffma2(acc[3][3], h3, wB.y);
        }
    }
    __syncthreads();   // all Phase-B reads of SCR done before epilogue overwrites

    // ---- epilogue: silu*att into SCR as [c4][e][4] ----
#pragma unroll
    for (int ee = 0; ee < 4; ++ee) {
        int el = et + ee * 32;
        float att = sAtt[el];
#pragma unroll
        for (int q = 0; q < 2; ++q) {
            float v0, v1, v2, v3;
            unpack2(acc[ee][2 * q],     v0, v1);
            unpack2(acc[ee][2 * q + 1], v2, v3);
            *(float4*)(sSCR + (ct * 2 + q) * GSTRIDE + el * 4) =
                make_float4(siluf(v0) * att, siluf(v1) * att,
                            siluf(v2) * att, siluf(v3) * att);
        }
    }
    __syncthreads();

    // ---- coalesced REDG scatter ----
#pragma unroll
    for (int it = 0; it < 8; ++it) {
        int item = it * 256 + tid;   // 0..2047
        int e = item >> 4;
        int c = item & 15;
        float4 v = *(const float4*)(sSCR + c * GSTRIDE + e * 4);
        redAdd4(g_hneigh + (size_t)sDstA[e] * F + c * 4, v.x, v.y, v.z, v.w);
    }
}

// ================= K4: node MLP — FFMA2, 4 channels/thread, 16 nodes/block =================
__global__ void __launch_bounds__(256)
k4_node(const float* __restrict__ nf,
        const float* __restrict__ Wn1,
        const float* __restrict__ bn1,
        const float* __restrict__ Wn2,
        const float* __restrict__ bn2,
        float* __restrict__ out) {
    __shared__ __align__(16) float sIn[16 * 132];   // [node][128 padded to 132]
    __shared__ __align__(16) float sH1[16 * 68];    // [node][64 padded to 68]
    int tid = threadIdx.x;
    int nodeBase = blockIdx.x * 16;

    // stage inputs: 16 nodes x (64 nf + 64 hneigh) floats
#pragma unroll
    for (int it = 0; it < 2; ++it) {
        int item = it * 256 + tid;   // 0..511
        int n = item >> 5;           // node 0..15
        int q = item & 31;           // float4 idx 0..31
        float4 v = (q < 16)
            ? __ldg((const float4*)(nf + (size_t)(nodeBase + n) * F) + q)
            : *(const float4*)(g_hneigh + (size_t)(nodeBase + n) * F + (q - 16) * 4);
        *(float4*)(sIn + n * 132 + q * 4) = v;
    }
    __syncthreads();

    int n  = tid >> 4;          // node 0..15
    int cq = (tid & 15) * 4;    // channels cq..cq+3
    const float* xrow = sIn + n * 132;

    u64p a0, a1;
    {
        float4 b = __ldg((const float4*)(bn1 + cq));
        a0 = pack2(b.x, b.y); a1 = pack2(b.z, b.w);
    }
#pragma unroll 8
    for (int k = 0; k < 128; ++k) {
        float x = xrow[k];
        u64p xp = pack2(x, x);
        ulonglong2 w = __ldg((const ulonglong2*)(Wn1 + k * F + cq));
        ffma2(a0, xp, w.x); ffma2(a1, xp, w.y);
    }
    {
        float v0, v1, v2, v3;
        unpack2(a0, v0, v1); unpack2(a1, v2, v3);
        *(float4*)(sH1 + n * 68 + cq) =
            make_float4(siluf(v0), siluf(v1), siluf(v2), siluf(v3));
    }
    __syncthreads();

    const float* hrow = sH1 + n * 68;
    {
        float4 b = __ldg((const float4*)(bn2 + cq));
        a0 = pack2(b.x, b.y); a1 = pack2(b.z, b.w);
    }
#pragma unroll 8
    for (int k = 0; k < 64; ++k) {
        float x = hrow[k];
        u64p xp = pack2(x, x);
        ulonglong2 w = __ldg((const ulonglong2*)(Wn2 + k * F + cq));
        ffma2(a0, xp, w.x); ffma2(a1, xp, w.y);
    }
    float v0, v1, v2, v3;
    unpack2(a0, v0, v1); unpack2(a1, v2, v3);
    *(float4*)(out + (size_t)(nodeBase + n) * F + cq) = make_float4(v0, v1, v2, v3);
}

extern "C" void kernel_launch(void* const* d_in, const int* in_sizes, int n_in,
                              void* d_out, int out_size) {
    const float* nf    = (const float*)d_in[0];
    const float* coord = (const float*)d_in[1];
    const float* efeat = (const float*)d_in[2];
    const float* We1   = (const float*)d_in[3];
    const float* be1   = (const float*)d_in[4];
    const float* We2   = (const float*)d_in[5];
    const float* be2   = (const float*)d_in[6];
    const float* Wn1   = (const float*)d_in[7];
    const float* bn1   = (const float*)d_in[8];
    const float* Wn2   = (const float*)d_in[9];
    const float* bn2   = (const float*)d_in[10];
    const float* Wq    = (const float*)d_in[11];
    const float* Wk    = (const float*)d_in[12];
    const int*   src   = (const int*)d_in[13];
    const int*   dst   = (const int*)d_in[14];
    float* out = (float*)d_out;

    const int k3_smem = SM_FLOATS * (int)sizeof(float);
    cudaFuncSetAttribute(k3_message, cudaFuncAttributeMaxDynamicSharedMemorySize, k3_smem);

    k0_node_pre<<<NN / 4, 256>>>(nf, We1, Wk, Wq);
    k1_scores<<<EE / 128, 256>>>(coord, efeat, src, dst);
    k3_message<<<EE / EPB, 256, k3_smem>>>(efeat, We1, be1, We2, be2, src, dst);
    k4_node<<<NN / 16, 256>>>(nf, Wn1, bn1, Wn2, bn2, out);
}

// round 14
// speedup vs baseline: 1.4891x; 1.3506x over previous
#include <cuda_runtime.h>
#include <cuda_fp16.h>
#include <stdint.h>
#include <math.h>

#define NN 10000
#define EE 640000
#define F  64
#define EFD 16

typedef unsigned long long u64p;

// ---- scratch (device globals; no allocations allowed) ----
__device__ float g_Asrc[NN*F];
__device__ float g_Adst[NN*F];
__device__ float g_Kn[NN*F];
__device__ float g_Qn[NN*F];
__device__ float g_Qk[NN*EFD];
__device__ float g_qd2[NN];
__device__ float g_denom[NN];
__device__ float g_hneigh[NN*F];
__device__ float g_e[EE];      // holds exp(score) after K1
__device__ float g_dist[EE];

__device__ __forceinline__ float siluf(float x) { return x / (1.f + __expf(-x)); }

__device__ __forceinline__ void redAdd4(float* addr, float a, float b, float c, float d) {
    asm volatile("red.global.add.v4.f32 [%0], {%1,%2,%3,%4};"
                 :: "l"(addr), "f"(a), "f"(b), "f"(c), "f"(d) : "memory");
}

__device__ __forceinline__ u64p pack2(float x, float y) {
    u64p r; asm("mov.b64 %0, {%1,%2};" : "=l"(r) : "f"(x), "f"(y)); return r;
}
__device__ __forceinline__ void unpack2(u64p v, float& x, float& y) {
    asm("mov.b64 {%0,%1}, %2;" : "=f"(x), "=f"(y) : "l"(v));
}
__device__ __forceinline__ void ffma2(u64p& d, u64p a, u64p b) {
    asm("fma.rn.f32x2 %0, %1, %2, %0;" : "+l"(d) : "l"(a), "l"(b));
}

__device__ __forceinline__ uint32_t smem_u32(const void* p) {
    uint32_t a;
    asm("{ .reg .u64 t; cvta.to.shared.u64 t, %1; cvt.u32.u64 %0, t; }" : "=r"(a) : "l"(p));
    return a;
}
__device__ __forceinline__ uint32_t swz128(uint32_t x) { return x ^ ((x >> 3) & 0x70u); }

__device__ __forceinline__ void ldmx4(uint32_t& a0, uint32_t& a1, uint32_t& a2, uint32_t& a3,
                                      uint32_t addr) {
    asm volatile("ldmatrix.sync.aligned.m8n8.x4.shared.b16 {%0,%1,%2,%3}, [%4];"
                 : "=r"(a0), "=r"(a1), "=r"(a2), "=r"(a3) : "r"(addr));
}
__device__ __forceinline__ void ldmx2t(uint32_t& b0, uint32_t& b1, uint32_t addr) {
    asm volatile("ldmatrix.sync.aligned.m8n8.x2.trans.shared.b16 {%0,%1}, [%2];"
                 : "=r"(b0), "=r"(b1) : "r"(addr));
}
__device__ __forceinline__ void mma16816(float& d0, float& d1, float& d2, float& d3,
                                         uint32_t a0, uint32_t a1, uint32_t a2, uint32_t a3,
                                         uint32_t b0, uint32_t b1) {
    asm volatile("mma.sync.aligned.m16n8k16.row.col.f32.f16.f16.f32 "
                 "{%0,%1,%2,%3}, {%4,%5,%6,%7}, {%8,%9}, {%0,%1,%2,%3};"
                 : "+f"(d0), "+f"(d1), "+f"(d2), "+f"(d3)
                 : "r"(a0), "r"(a1), "r"(a2), "r"(a3), "r"(b0), "r"(b1));
}

// ================= K0: per-node precompute + init =================
__global__ void k0_node_pre(const float* __restrict__ nf,
                            const float* __restrict__ We1,
                            const float* __restrict__ Wk,
                            const float* __restrict__ Wq) {
    __shared__ __align__(16) float srow[4 * F];
    __shared__ __align__(16) float sQ[4 * F];
    int tid = threadIdx.x;
    int nodeBase = blockIdx.x * 4;
    srow[tid] = nf[(size_t)nodeBase * F + tid];
    __syncthreads();
    int ln = tid >> 6;
    int c  = tid & 63;
    int node = nodeBase + ln;
    const float* r = srow + ln * F;
    float a0 = 0.f, a1 = 0.f, a2 = 0.f, a3 = 0.f;
#pragma unroll 8
    for (int k = 0; k < F; ++k) {
        float x = r[k];
        a0 += x * __ldg(We1 + k * F + c);
        a1 += x * __ldg(We1 + (F + k) * F + c);
        a2 += x * __ldg(Wk  + k * F + c);
        a3 += x * __ldg(Wq  + k * F + c);
    }
    g_Asrc[node * F + c] = a0;
    g_Adst[node * F + c] = a1;
    g_Kn  [node * F + c] = a2;
    g_Qn  [node * F + c] = a3;
    sQ[ln * F + c] = a3;
    g_hneigh[node * F + c] = 0.f;
    if (c == 0) g_denom[node] = 0.f;
    __syncthreads();
    if (tid < 64) {
        int ln2 = tid >> 4, j = tid & 15;
        const float* q = sQ + ln2 * F;
        float acc = 0.f;
#pragma unroll 8
        for (int k = 0; k < F; ++k) acc += q[k] * __ldg(Wk + (65 + j) * F + k);
        g_Qk[(nodeBase + ln2) * EFD + j] = acc;
    } else if (tid < 68) {
        int ln2 = tid - 64;
        const float* q = sQ + ln2 * F;
        float acc = 0.f;
#pragma unroll 8
        for (int k = 0; k < F; ++k) acc += q[k] * __ldg(Wk + 64 * F + k);
        g_qd2[nodeBase + ln2] = acc;
    }
}

// ================= K1: edge scores -> exp(e), denom atomicAdd =================
__global__ void __launch_bounds__(256)
k1_scores(const float* __restrict__ coord,
          const float* __restrict__ efeat,
          const int* __restrict__ src,
          const int* __restrict__ dst) {
    int tid = threadIdx.x;
    int warp = tid >> 5, lane = tid & 31;
    int sub = lane >> 4, c = lane & 15;
    int base = blockIdx.x * 128 + warp * 16;

#pragma unroll
    for (int it = 0; it < 8; ++it) {
        int e = base + it * 2 + sub;
        int s = __ldg(&src[e]);
        int d = __ldg(&dst[e]);

        float4 kv = __ldg((const float4*)(g_Kn + (size_t)s * F) + c);
        float4 qv = __ldg((const float4*)(g_Qn + (size_t)d * F) + c);
        float part = kv.x * qv.x + kv.y * qv.y + kv.z * qv.z + kv.w * qv.w;

        if (c < 4) {
            float4 ev = __ldg((const float4*)(efeat + (size_t)e * EFD) + c);
            float4 qk = __ldg((const float4*)(g_Qk + (size_t)d * EFD) + c);
            part += ev.x * qk.x + ev.y * qk.y + ev.z * qk.z + ev.w * qk.w;
        }

        float dist = 0.f;
        if (c == 0) {
            float dx = __ldg(&coord[s * 3 + 0]) - __ldg(&coord[d * 3 + 0]);
            float dy = __ldg(&coord[s * 3 + 1]) - __ldg(&coord[d * 3 + 1]);
            float dz = __ldg(&coord[s * 3 + 2]) - __ldg(&coord[d * 3 + 2]);
            dist = sqrtf(dx * dx + dy * dy + dz * dz);
            part += dist * __ldg(&g_qd2[d]);
        }

#pragma unroll
        for (int o = 8; o; o >>= 1)
            part += __shfl_down_sync(0xffffffffu, part, o, 16);

        if (c == 0) {
            float v = __expf(part * 0.125f);
            g_e[e] = v;
            g_dist[e] = dist;
            atomicAdd(&g_denom[d], v);
        }
    }
}

// ================= K3: Phase A FFMA2 + Phase B mma.sync (HMMA) + scatter =================
// 128 edges/block, 256 threads, 39.4KB smem -> 4 blocks/SM.
// byte layout:
//   [0,16384)      A-tile fp16 [128e][64h], SW128 swizzled (gather writes pre; Phase A RMW -> h1)
//   [16384,24576)  B-tile fp16 [64h][64c], SW128 (We2)
//   [24576,37904)  X: efT [17][132] fl + Wa [17][64] fl   (dies after Phase A)
//   epilogue SCR [16 c4][516] fl overlays bytes [0,33024) after MMA
//   [37904,...)    att[128], dst[128], b1[64], b2[64]
#define EPB 128
#define GSTRIDE 516
#define EFTS 132
#define SM_B_BYTE  16384
#define SM_X_FLT   6144
#define SM_ATT_FLT 9476
#define SM_DST_FLT 9604
#define SM_B1_FLT  9732
#define SM_B2_FLT  9796
#define SM_FLOATS  9860

__global__ void __launch_bounds__(256, 4)
k3_message(const float* __restrict__ efeat,
           const float* __restrict__ We1,
           const float* __restrict__ be1,
           const float* __restrict__ We2,
           const float* __restrict__ be2,
           const int* __restrict__ src,
           const int* __restrict__ dst) {
    extern __shared__ __align__(1024) float sm[];
    char* smb = (char*)sm;
    float* sEfT  = sm + SM_X_FLT;
    float* sWa   = sm + SM_X_FLT + 17 * EFTS;
    float* sAtt  = sm + SM_ATT_FLT;
    int*   sDstA = (int*)(sm + SM_DST_FLT);
    float* sB1   = sm + SM_B1_FLT;
    float* sB2   = sm + SM_B2_FLT;

    int tid = threadIdx.x;
    int lane = tid & 31;
    int wid = tid >> 5;
    int blockbase = blockIdx.x * EPB;
    uint32_t sbase = smem_u32(sm);

    // ---- stage Wa (rows: 0=dist row We1[128], 1..16 = We1[129+j]) + biases ----
    for (int i = tid; i < 17 * F; i += 256) sWa[i] = We1[128 * F + i];
    if (tid >= 192) {
        int t = tid - 192;
        sB1[t] = be1[t];
        sB2[t] = be2[t];
    }
    // ---- per-edge scalars (dist -> efT row 0) ----
    if (tid < 128) {
        int e = blockbase + tid;
        int d = __ldg(&dst[e]);
        sDstA[tid] = d;
        sAtt[tid] = __fdividef(__ldg(&g_e[e]), __ldg(&g_denom[d]));
        sEfT[tid] = __ldg(&g_dist[e]);
    }
    // ---- stage efeat transposed into efT rows 1..16 ----
#pragma unroll
    for (int it = 0; it < 2; ++it) {
        int item = it * 256 + tid;
        int e = item >> 2;
        int c = item & 3;
        float4 v = __ldg((const float4*)(efeat + (size_t)(blockbase + e) * EFD) + c);
        sEfT[(c * 4 + 1) * EFTS + e] = v.x;
        sEfT[(c * 4 + 2) * EFTS + e] = v.y;
        sEfT[(c * 4 + 3) * EFTS + e] = v.z;
        sEfT[(c * 4 + 4) * EFTS + e] = v.w;
    }
    // ---- stage B-tile: We2 [h][c] as fp16, SW128 ----
#pragma unroll
    for (int it = 0; it < 16; ++it) {
        int i = it * 256 + tid;      // 0..4095
        int h = i >> 6, c = i & 63;
        *(__half*)(smb + SM_B_BYTE + swz128((uint32_t)(h * 128 + c * 2))) =
            __float2half_rn(We2[h * F + c]);
    }
    // ---- coalesced gather of pre = Asrc[s]+Adst[d] into fp16 A-tile ----
#pragma unroll
    for (int it = 0; it < 8; ++it) {
        int item = it * 256 + tid;   // 0..2047
        int e = item >> 4;
        int c = item & 15;           // 4-h group
        int s = __ldg(&src[blockbase + e]);
        int d = __ldg(&dst[blockbase + e]);
        float4 a = __ldg((const float4*)(g_Asrc + (size_t)s * F) + c);
        float4 b = __ldg((const float4*)(g_Adst + (size_t)d * F) + c);
        __half2 p0 = __floats2half2_rn(a.x + b.x, a.y + b.y);
        __half2 p1 = __floats2half2_rn(a.z + b.z, a.w + b.w);
        uint2 u;
        u.x = *(uint32_t*)&p0;
        u.y = *(uint32_t*)&p1;
        *(uint2*)(smb + swz128((uint32_t)(e * 128 + c * 8))) = u;
    }
    __syncthreads();

    // ---------------- Phase A: GEMM K=17, tile 4 edges x 8 h, in-place fp16 ----------------
    {
        int ea = (tid & 31) * 4;
        int ht = tid >> 5;

        u64p a[4][4];
        {
            const ulonglong2* b1p = (const ulonglong2*)(sB1 + ht * 8);
            ulonglong2 bA = b1p[0], bB = b1p[1];
#pragma unroll
            for (int e = 0; e < 4; ++e) {
                a[e][0] = bA.x; a[e][1] = bA.y;
                a[e][2] = bB.x; a[e][3] = bB.y;
            }
        }

#pragma unroll
        for (int j = 0; j < 17; ++j) {
            float4 ef4 = *(const float4*)(sEfT + j * EFTS + ea);
            const ulonglong2* wp = (const ulonglong2*)(sWa + j * F + ht * 8);
            ulonglong2 wA = wp[0], wB = wp[1];
            u64p p0 = pack2(ef4.x, ef4.x);
            u64p p1 = pack2(ef4.y, ef4.y);
            u64p p2 = pack2(ef4.z, ef4.z);
            u64p p3 = pack2(ef4.w, ef4.w);
            ffma2(a[0][0], p0, wA.x); ffma2(a[0][1], p0, wA.y);
            ffma2(a[0][2], p0, wB.x); ffma2(a[0][3], p0, wB.y);
            ffma2(a[1][0], p1, wA.x); ffma2(a[1][1], p1, wA.y);
            ffma2(a[1][2], p1, wB.x); ffma2(a[1][3], p1, wB.y);
            ffma2(a[2][0], p2, wA.x); ffma2(a[2][1], p2, wA.y);
            ffma2(a[2][2], p2, wB.x); ffma2(a[2][3], p2, wB.y);
            ffma2(a[3][0], p3, wA.x); ffma2(a[3][1], p3, wA.y);
            ffma2(a[3][2], p3, wB.x); ffma2(a[3][3], p3, wB.y);
        }

        // h1 = silu(pre + acc), in place in the fp16 A-tile
#pragma unroll
        for (int e = 0; e < 4; ++e) {
            int el = ea + e;
            char* slot = smb + swz128((uint32_t)(el * 128 + ht * 16));
            uint4 raw = *(uint4*)slot;
            float2 f0 = __half22float2(*(__half2*)&raw.x);
            float2 f1 = __half22float2(*(__half2*)&raw.y);
            float2 f2 = __half22float2(*(__half2*)&raw.z);
            float2 f3 = __half22float2(*(__half2*)&raw.w);
            float g0, g1, g2, g3, g4, g5, g6, g7;
            unpack2(a[e][0], g0, g1);
            unpack2(a[e][1], g2, g3);
            unpack2(a[e][2], g4, g5);
            unpack2(a[e][3], g6, g7);
            __half2 o0 = __floats2half2_rn(siluf(f0.x + g0), siluf(f0.y + g1));
            __half2 o1 = __floats2half2_rn(siluf(f1.x + g2), siluf(f1.y + g3));
            __half2 o2 = __floats2half2_rn(siluf(f2.x + g4), siluf(f2.y + g5));
            __half2 o3 = __floats2half2_rn(siluf(f3.x + g6), siluf(f3.y + g7));
            uint4 out;
            out.x = *(uint32_t*)&o0; out.y = *(uint32_t*)&o1;
            out.z = *(uint32_t*)&o2; out.w = *(uint32_t*)&o3;
            *(uint4*)slot = out;
        }
    }
    __syncthreads();

    // ---------------- Phase B: mma.sync, warp = 16 edges x 64 c ----------------
    float acc[8][4];
#pragma unroll
    for (int j = 0; j < 8; ++j)
        acc[j][0] = acc[j][1] = acc[j][2] = acc[j][3] = 0.f;

    {
        int ew = wid * 16;
        uint32_t arow = (uint32_t)((ew + (lane & 15)) * 128) + ((lane >> 4) << 4);
        uint32_t brow = (uint32_t)((lane & 15) * 128);
#pragma unroll
        for (int kk = 0; kk < 4; ++kk) {
            uint32_t a0, a1, a2, a3;
            ldmx4(a0, a1, a2, a3, sbase + swz128(arow + kk * 32));
#pragma unroll
            for (int j = 0; j < 8; ++j) {
                uint32_t b0, b1;
                ldmx2t(b0, b1, sbase + SM_B_BYTE + swz128(brow + kk * 16 * 128 + j * 16));
                mma16816(acc[j][0], acc[j][1], acc[j][2], acc[j][3],
                         a0, a1, a2, a3, b0, b1);
            }
        }
    }
    __syncthreads();   // A/B tiles dead; epilogue overlays them

    // ---- epilogue: silu(d + b2) * att into SCR [c4][e][4] ----
    {
        int ew = wid * 16;
        int g = lane >> 2;
        int tg = lane & 3;
        int r0 = ew + g, r1 = r0 + 8;
        float att0 = sAtt[r0], att1 = sAtt[r1];
#pragma unroll
        for (int j = 0; j < 8; ++j) {
            int c = j * 8 + tg * 2;
            float b2a = sB2[c], b2b = sB2[c + 1];
            float* base = sm + (c >> 2) * GSTRIDE + (c & 3);
            *(float2*)(base + r0 * 4) =
                make_float2(siluf(acc[j][0] + b2a) * att0, siluf(acc[j][1] + b2b) * att0);
            *(float2*)(base + r1 * 4) =
                make_float2(siluf(acc[j][2] + b2a) * att1, siluf(acc[j][3] + b2b) * att1);
        }
    }
    __syncthreads();

    // ---- coalesced REDG scatter ----
#pragma unroll
    for (int it = 0; it < 8; ++it) {
        int item = it * 256 + tid;   // 0..2047
        int e = item >> 4;
        int c = item & 15;
        float4 v = *(const float4*)(sm + c * GSTRIDE + e * 4);
        redAdd4(g_hneigh + (size_t)sDstA[e] * F + c * 4, v.x, v.y, v.z, v.w);
    }
}

// ================= K4: node MLP — FFMA2, 4 channels/thread, 16 nodes/block =================
__global__ void __launch_bounds__(256)
k4_node(const float* __restrict__ nf,
        const float* __restrict__ Wn1,
        const float* __restrict__ bn1,
        const float* __restrict__ Wn2,
        const float* __restrict__ bn2,
        float* __restrict__ out) {
    __shared__ __align__(16) float sIn[16 * 132];
    __shared__ __align__(16) float sH1[16 * 68];
    int tid = threadIdx.x;
    int nodeBase = blockIdx.x * 16;

#pragma unroll
    for (int it = 0; it < 2; ++it) {
        int item = it * 256 + tid;
        int n = item >> 5;
        int q = item & 31;
        float4 v = (q < 16)
            ? __ldg((const float4*)(nf + (size_t)(nodeBase + n) * F) + q)
            : *(const float4*)(g_hneigh + (size_t)(nodeBase + n) * F + (q - 16) * 4);
        *(float4*)(sIn + n * 132 + q * 4) = v;
    }
    __syncthreads();

    int n  = tid >> 4;
    int cq = (tid & 15) * 4;
    const float* xrow = sIn + n * 132;

    u64p a0, a1;
    {
        float4 b = __ldg((const float4*)(bn1 + cq));
        a0 = pack2(b.x, b.y); a1 = pack2(b.z, b.w);
    }
#pragma unroll 8
    for (int k = 0; k < 128; ++k) {
        float x = xrow[k];
        u64p xp = pack2(x, x);
        ulonglong2 w = __ldg((const ulonglong2*)(Wn1 + k * F + cq));
        ffma2(a0, xp, w.x); ffma2(a1, xp, w.y);
    }
    {
        float v0, v1, v2, v3;
        unpack2(a0, v0, v1); unpack2(a1, v2, v3);
        *(float4*)(sH1 + n * 68 + cq) =
            make_float4(siluf(v0), siluf(v1), siluf(v2), siluf(v3));
    }
    __syncthreads();

    const float* hrow = sH1 + n * 68;
    {
        float4 b = __ldg((const float4*)(bn2 + cq));
        a0 = pack2(b.x, b.y); a1 = pack2(b.z, b.w);
    }
#pragma unroll 8
    for (int k = 0; k < 64; ++k) {
        float x = hrow[k];
        u64p xp = pack2(x, x);
        ulonglong2 w = __ldg((const ulonglong2*)(Wn2 + k * F + cq));
        ffma2(a0, xp, w.x); ffma2(a1, xp, w.y);
    }
    float v0, v1, v2, v3;
    unpack2(a0, v0, v1); unpack2(a1, v2, v3);
    *(float4*)(out + (size_t)(nodeBase + n) * F + cq) = make_float4(v0, v1, v2, v3);
}

extern "C" void kernel_launch(void* const* d_in, const int* in_sizes, int n_in,
                              void* d_out, int out_size) {
    const float* nf    = (const float*)d_in[0];
    const float* coord = (const float*)d_in[1];
    const float* efeat = (const float*)d_in[2];
    const float* We1   = (const float*)d_in[3];
    const float* be1   = (const float*)d_in[4];
    const float* We2   = (const float*)d_in[5];
    const float* be2   = (const float*)d_in[6];
    const float* Wn1   = (const float*)d_in[7];
    const float* bn1   = (const float*)d_in[8];
    const float* Wn2   = (const float*)d_in[9];
    const float* bn2   = (const float*)d_in[10];
    const float* Wq    = (const float*)d_in[11];
    const float* Wk    = (const float*)d_in[12];
    const int*   src   = (const int*)d_in[13];
    const int*   dst   = (const int*)d_in[14];
    float* out = (float*)d_out;

    const int k3_smem = SM_FLOATS * (int)sizeof(float);
    cudaFuncSetAttribute(k3_message, cudaFuncAttributeMaxDynamicSharedMemorySize, k3_smem);

    k0_node_pre<<<NN / 4, 256>>>(nf, We1, Wk, Wq);
    k1_scores<<<EE / 128, 256>>>(coord, efeat, src, dst);
    k3_message<<<EE / EPB, 256, k3_smem>>>(efeat, We1, be1, We2, be2, src, dst);
    k4_node<<<NN / 16, 256>>>(nf, Wn1, bn1, Wn2, bn2, out);
}

// round 15
// speedup vs baseline: 1.5551x; 1.0443x over previous
#include <cuda_runtime.h>
#include <cuda_fp16.h>
#include <stdint.h>
#include <math.h>

#define NN 10000
#define EE 640000
#define F  64
#define EFD 16

typedef unsigned long long u64p;

// ---- scratch (device globals; no allocations allowed) ----
__device__ float g_Asrc[NN*F];
__device__ float g_Adst[NN*F];
__device__ float g_Kn[NN*F];
__device__ float g_Qn[NN*F];
__device__ float g_Qk[NN*EFD];
__device__ float g_qd2[NN];
__device__ float g_denom[NN];
__device__ float g_hneigh[NN*F];
__device__ float g_e[EE];      // holds exp(score) after K1
__device__ float g_dist[EE];

__device__ __forceinline__ float siluf(float x) { return x / (1.f + __expf(-x)); }

__device__ __forceinline__ void redAdd4(float* addr, float a, float b, float c, float d) {
    asm volatile("red.global.add.v4.f32 [%0], {%1,%2,%3,%4};"
                 :: "l"(addr), "f"(a), "f"(b), "f"(c), "f"(d) : "memory");
}

__device__ __forceinline__ u64p pack2(float x, float y) {
    u64p r; asm("mov.b64 %0, {%1,%2};" : "=l"(r) : "f"(x), "f"(y)); return r;
}
__device__ __forceinline__ void unpack2(u64p v, float& x, float& y) {
    asm("mov.b64 {%0,%1}, %2;" : "=f"(x), "=f"(y) : "l"(v));
}
__device__ __forceinline__ void ffma2(u64p& d, u64p a, u64p b) {
    asm("fma.rn.f32x2 %0, %1, %2, %0;" : "+l"(d) : "l"(a), "l"(b));
}

__device__ __forceinline__ uint32_t smem_u32(const void* p) {
    uint32_t a;
    asm("{ .reg .u64 t; cvta.to.shared.u64 t, %1; cvt.u32.u64 %0, t; }" : "=r"(a) : "l"(p));
    return a;
}
__device__ __forceinline__ uint32_t swz128(uint32_t x) { return x ^ ((x >> 3) & 0x70u); }
__device__ __forceinline__ uint32_t swz64(uint32_t x)  { return x ^ ((x >> 3) & 0x30u); }

__device__ __forceinline__ void ldmx4(uint32_t& a0, uint32_t& a1, uint32_t& a2, uint32_t& a3,
                                      uint32_t addr) {
    asm volatile("ldmatrix.sync.aligned.m8n8.x4.shared.b16 {%0,%1,%2,%3}, [%4];"
                 : "=r"(a0), "=r"(a1), "=r"(a2), "=r"(a3) : "r"(addr));
}
__device__ __forceinline__ void ldmx2t(uint32_t& b0, uint32_t& b1, uint32_t addr) {
    asm volatile("ldmatrix.sync.aligned.m8n8.x2.trans.shared.b16 {%0,%1}, [%2];"
                 : "=r"(b0), "=r"(b1) : "r"(addr));
}
__device__ __forceinline__ void mma16816(float& d0, float& d1, float& d2, float& d3,
                                         uint32_t a0, uint32_t a1, uint32_t a2, uint32_t a3,
                                         uint32_t b0, uint32_t b1) {
    asm volatile("mma.sync.aligned.m16n8k16.row.col.f32.f16.f16.f32 "
                 "{%0,%1,%2,%3}, {%4,%5,%6,%7}, {%8,%9}, {%0,%1,%2,%3};"
                 : "+f"(d0), "+f"(d1), "+f"(d2), "+f"(d3)
                 : "r"(a0), "r"(a1), "r"(a2), "r"(a3), "r"(b0), "r"(b1));
}

// ================= K0: per-node precompute + init =================
__global__ void k0_node_pre(const float* __restrict__ nf,
                            const float* __restrict__ We1,
                            const float* __restrict__ Wk,
                            const float* __restrict__ Wq) {
    __shared__ __align__(16) float srow[4 * F];
    __shared__ __align__(16) float sQ[4 * F];
    int tid = threadIdx.x;
    int nodeBase = blockIdx.x * 4;
    srow[tid] = nf[(size_t)nodeBase * F + tid];
    __syncthreads();
    int ln = tid >> 6;
    int c  = tid & 63;
    int node = nodeBase + ln;
    const float* r = srow + ln * F;
    float a0 = 0.f, a1 = 0.f, a2 = 0.f, a3 = 0.f;
#pragma unroll 8
    for (int k = 0; k < F; ++k) {
        float x = r[k];
        a0 += x * __ldg(We1 + k * F + c);
        a1 += x * __ldg(We1 + (F + k) * F + c);
        a2 += x * __ldg(Wk  + k * F + c);
        a3 += x * __ldg(Wq  + k * F + c);
    }
    g_Asrc[node * F + c] = a0;
    g_Adst[node * F + c] = a1;
    g_Kn  [node * F + c] = a2;
    g_Qn  [node * F + c] = a3;
    sQ[ln * F + c] = a3;
    g_hneigh[node * F + c] = 0.f;
    if (c == 0) g_denom[node] = 0.f;
    __syncthreads();
    if (tid < 64) {
        int ln2 = tid >> 4, j = tid & 15;
        const float* q = sQ + ln2 * F;
        float acc = 0.f;
#pragma unroll 8
        for (int k = 0; k < F; ++k) acc += q[k] * __ldg(Wk + (65 + j) * F + k);
        g_Qk[(nodeBase + ln2) * EFD + j] = acc;
    } else if (tid < 68) {
        int ln2 = tid - 64;
        const float* q = sQ + ln2 * F;
        float acc = 0.f;
#pragma unroll 8
        for (int k = 0; k < F; ++k) acc += q[k] * __ldg(Wk + 64 * F + k);
        g_qd2[nodeBase + ln2] = acc;
    }
}

// ================= K1: edge scores -> exp(e), denom atomicAdd =================
__global__ void __launch_bounds__(256)
k1_scores(const float* __restrict__ coord,
          const float* __restrict__ efeat,
          const int* __restrict__ src,
          const int* __restrict__ dst) {
    int tid = threadIdx.x;
    int warp = tid >> 5, lane = tid & 31;
    int sub = lane >> 4, c = lane & 15;
    int base = blockIdx.x * 128 + warp * 16;

#pragma unroll
    for (int it = 0; it < 8; ++it) {
        int e = base + it * 2 + sub;
        int s = __ldg(&src[e]);
        int d = __ldg(&dst[e]);

        float4 kv = __ldg((const float4*)(g_Kn + (size_t)s * F) + c);
        float4 qv = __ldg((const float4*)(g_Qn + (size_t)d * F) + c);
        float part = kv.x * qv.x + kv.y * qv.y + kv.z * qv.z + kv.w * qv.w;

        if (c < 4) {
            float4 ev = __ldg((const float4*)(efeat + (size_t)e * EFD) + c);
            float4 qk = __ldg((const float4*)(g_Qk + (size_t)d * EFD) + c);
            part += ev.x * qk.x + ev.y * qk.y + ev.z * qk.z + ev.w * qk.w;
        }

        float dist = 0.f;
        if (c == 0) {
            float dx = __ldg(&coord[s * 3 + 0]) - __ldg(&coord[d * 3 + 0]);
            float dy = __ldg(&coord[s * 3 + 1]) - __ldg(&coord[d * 3 + 1]);
            float dz = __ldg(&coord[s * 3 + 2]) - __ldg(&coord[d * 3 + 2]);
            dist = sqrtf(dx * dx + dy * dy + dz * dz);
            part += dist * __ldg(&g_qd2[d]);
        }

#pragma unroll
        for (int o = 8; o; o >>= 1)
            part += __shfl_down_sync(0xffffffffu, part, o, 16);

        if (c == 0) {
            float v = __expf(part * 0.125f);
            g_e[e] = v;
            g_dist[e] = dist;
            atomicAdd(&g_denom[d], v);
        }
    }
}

// ================= K3: dual mma.sync edge message + scatter =================
// 128 edges/block, 256 threads, 38.4KB smem -> 4 blocks/SM.
// byte layout:
//   [0,16384)      A-tile fp16 [128e][64h], SW128 (gather writes pre; Phase A RMW -> h1)
//   [16384,24576)  B-tile fp16 [64h][64c], SW128 (We2)
//   [24576,28672)  Wa fp16 [32k][64h], SW128 (k0-15 ef rows, k16 dist row, rest 0)
//   [28672,36864)  efx fp16 [128e][32k], 64B rows SW64 (k0-15 ef, k16 dist, rest 0)
//   epilogue SCR [16 c4][516] fl overlays bytes [0,33024) after Phase B
//   floats >= 9216: att[128], dst[128], b1[64], b2[64]
#define EPB 128
#define GSTRIDE 516
#define SM_B_BYTE   16384
#define SM_WA_BYTE  24576
#define SM_EFX_BYTE 28672
#define SM_ATT_FLT  9216
#define SM_DST_FLT  9344
#define SM_B1_FLT   9472
#define SM_B2_FLT   9536
#define SM_FLOATS   9600

__global__ void __launch_bounds__(256, 4)
k3_message(const float* __restrict__ efeat,
           const float* __restrict__ We1,
           const float* __restrict__ be1,
           const float* __restrict__ We2,
           const float* __restrict__ be2,
           const int* __restrict__ src,
           const int* __restrict__ dst) {
    extern __shared__ __align__(1024) float sm[];
    char* smb = (char*)sm;
    float* sAtt  = sm + SM_ATT_FLT;
    int*   sDstA = (int*)(sm + SM_DST_FLT);
    float* sB1   = sm + SM_B1_FLT;
    float* sB2   = sm + SM_B2_FLT;

    int tid = threadIdx.x;
    int lane = tid & 31;
    int wid = tid >> 5;
    int blockbase = blockIdx.x * EPB;
    uint32_t sbase = smem_u32(sm);

    // ---- stage Wa fp16 [32k][64h]: k0-15 = We1[129+k], k16 = We1[128], rest 0 ----
#pragma unroll
    for (int it = 0; it < 8; ++it) {
        int i = it * 256 + tid;      // 0..2047
        int k = i >> 6, h = i & 63;
        float v = (k < 16) ? We1[(129 + k) * F + h]
                           : (k == 16 ? We1[128 * F + h] : 0.f);
        *(__half*)(smb + SM_WA_BYTE + swz128((uint32_t)(k * 128 + h * 2))) =
            __float2half_rn(v);
    }
    if (tid >= 192) {
        int t = tid - 192;
        sB1[t] = be1[t];
        sB2[t] = be2[t];
    }
    // ---- per-edge scalars + efx upper half-row (k16 = dist, k17-31 = 0) ----
    if (tid < 128) {
        int e = blockbase + tid;
        int d = __ldg(&dst[e]);
        sDstA[tid] = d;
        sAtt[tid] = __fdividef(__ldg(&g_e[e]), __ldg(&g_denom[d]));
        float dist = __ldg(&g_dist[e]);
        __half2 dz = __floats2half2_rn(dist, 0.f);
        uint4 u0;
        u0.x = *(uint32_t*)&dz; u0.y = 0; u0.z = 0; u0.w = 0;
        *(uint4*)(smb + SM_EFX_BYTE + swz64((uint32_t)(tid * 64 + 32))) = u0;
        uint4 z; z.x = z.y = z.z = z.w = 0;
        *(uint4*)(smb + SM_EFX_BYTE + swz64((uint32_t)(tid * 64 + 48))) = z;
    }
    // ---- efx lower half: k0-15 = efeat fp16 ----
#pragma unroll
    for (int it = 0; it < 2; ++it) {
        int item = it * 256 + tid;   // 0..511
        int e = item >> 2;
        int c = item & 3;
        float4 v = __ldg((const float4*)(efeat + (size_t)(blockbase + e) * EFD) + c);
        __half2 h0 = __floats2half2_rn(v.x, v.y);
        __half2 h1 = __floats2half2_rn(v.z, v.w);
        uint2 u;
        u.x = *(uint32_t*)&h0;
        u.y = *(uint32_t*)&h1;
        *(uint2*)(smb + SM_EFX_BYTE + swz64((uint32_t)(e * 64 + c * 8))) = u;
    }
    // ---- stage B-tile: We2 [h][c] fp16, SW128 ----
#pragma unroll
    for (int it = 0; it < 16; ++it) {
        int i = it * 256 + tid;      // 0..4095
        int h = i >> 6, c = i & 63;
        *(__half*)(smb + SM_B_BYTE + swz128((uint32_t)(h * 128 + c * 2))) =
            __float2half_rn(We2[h * F + c]);
    }
    // ---- coalesced gather of pre = Asrc[s]+Adst[d] into fp16 A-tile ----
#pragma unroll
    for (int it = 0; it < 8; ++it) {
        int item = it * 256 + tid;   // 0..2047
        int e = item >> 4;
        int c = item & 15;           // 4-h group
        int s = __ldg(&src[blockbase + e]);
        int d = __ldg(&dst[blockbase + e]);
        float4 a = __ldg((const float4*)(g_Asrc + (size_t)s * F) + c);
        float4 b = __ldg((const float4*)(g_Adst + (size_t)d * F) + c);
        __half2 p0 = __floats2half2_rn(a.x + b.x, a.y + b.y);
        __half2 p1 = __floats2half2_rn(a.z + b.z, a.w + b.w);
        uint2 u;
        u.x = *(uint32_t*)&p0;
        u.y = *(uint32_t*)&p1;
        *(uint2*)(smb + swz128((uint32_t)(e * 128 + c * 8))) = u;
    }
    __syncthreads();

    int ew = wid * 16;

    // ---------------- Phase A: mma.sync, warp = 16e x 64h, K=32 ----------------
    {
        float pacc[8][4];
#pragma unroll
        for (int j = 0; j < 8; ++j)
            pacc[j][0] = pacc[j][1] = pacc[j][2] = pacc[j][3] = 0.f;

        uint32_t arow = (uint32_t)((ew + (lane & 15)) * 64) + ((lane >> 4) << 4);
        uint32_t brow = (uint32_t)((lane & 15) * 128);
#pragma unroll
        for (int kk = 0; kk < 2; ++kk) {
            uint32_t a0, a1, a2, a3;
            ldmx4(a0, a1, a2, a3, sbase + SM_EFX_BYTE + swz64(arow + kk * 32));
#pragma unroll
            for (int j = 0; j < 8; ++j) {
                uint32_t b0, b1;
                ldmx2t(b0, b1, sbase + SM_WA_BYTE + swz128(brow + kk * 16 * 128 + j * 16));
                mma16816(pacc[j][0], pacc[j][1], pacc[j][2], pacc[j][3],
                         a0, a1, a2, a3, b0, b1);
            }
        }

        // h1 = silu(pre + b1 + acc), RMW in A-tile at D-fragment coords
        int g = lane >> 2, tg = lane & 3;
        int r0 = ew + g, r1 = r0 + 8;
#pragma unroll
        for (int j = 0; j < 8; ++j) {
            int c = j * 8 + tg * 2;
            float b1a = sB1[c], b1b = sB1[c + 1];
            char* p0 = smb + swz128((uint32_t)(r0 * 128 + c * 2));
            char* p1 = smb + swz128((uint32_t)(r1 * 128 + c * 2));
            float2 f0 = __half22float2(*(__half2*)p0);
            float2 f1 = __half22float2(*(__half2*)p1);
            __half2 o0 = __floats2half2_rn(siluf(f0.x + pacc[j][0] + b1a),
                                           siluf(f0.y + pacc[j][1] + b1b));
            __half2 o1 = __floats2half2_rn(siluf(f1.x + pacc[j][2] + b1a),
                                           siluf(f1.y + pacc[j][3] + b1b));
            *(__half2*)p0 = o0;
            *(__half2*)p1 = o1;
        }
    }
    __syncthreads();

    // ---------------- Phase B: mma.sync, warp = 16e x 64c ----------------
    float acc[8][4];
#pragma unroll
    for (int j = 0; j < 8; ++j)
        acc[j][0] = acc[j][1] = acc[j][2] = acc[j][3] = 0.f;

    {
        uint32_t arow = (uint32_t)((ew + (lane & 15)) * 128) + ((lane >> 4) << 4);
        uint32_t brow = (uint32_t)((lane & 15) * 128);
#pragma unroll
        for (int kk = 0; kk < 4; ++kk) {
            uint32_t a0, a1, a2, a3;
            ldmx4(a0, a1, a2, a3, sbase + swz128(arow + kk * 32));
#pragma unroll
            for (int j = 0; j < 8; ++j) {
                uint32_t b0, b1;
                ldmx2t(b0, b1, sbase + SM_B_BYTE + swz128(brow + kk * 16 * 128 + j * 16));
                mma16816(acc[j][0], acc[j][1], acc[j][2], acc[j][3],
                         a0, a1, a2, a3, b0, b1);
            }
        }
    }
    __syncthreads();   // A/B tiles dead; epilogue overlays them

    // ---- epilogue: silu(d + b2) * att into SCR [c4][e][4] ----
    {
        int g = lane >> 2;
        int tg = lane & 3;
        int r0 = ew + g, r1 = r0 + 8;
        float att0 = sAtt[r0], att1 = sAtt[r1];
#pragma unroll
        for (int j = 0; j < 8; ++j) {
            int c = j * 8 + tg * 2;
            float b2a = sB2[c], b2b = sB2[c + 1];
            float* base = sm + (c >> 2) * GSTRIDE + (c & 3);
            *(float2*)(base + r0 * 4) =
                make_float2(siluf(acc[j][0] + b2a) * att0, siluf(acc[j][1] + b2b) * att0);
            *(float2*)(base + r1 * 4) =
                make_float2(siluf(acc[j][2] + b2a) * att1, siluf(acc[j][3] + b2b) * att1);
        }
    }
    __syncthreads();

    // ---- coalesced REDG scatter ----
#pragma unroll
    for (int it = 0; it < 8; ++it) {
        int item = it * 256 + tid;   // 0..2047
        int e = item >> 4;
        int c = item & 15;
        float4 v = *(const float4*)(sm + c * GSTRIDE + e * 4);
        redAdd4(g_hneigh + (size_t)sDstA[e] * F + c * 4, v.x, v.y, v.z, v.w);
    }
}

// ================= K4: node MLP — FFMA2, 4 channels/thread, 16 nodes/block =================
__global__ void __launch_bounds__(256)
k4_node(const float* __restrict__ nf,
        const float* __restrict__ Wn1,
        const float* __restrict__ bn1,
        const float* __restrict__ Wn2,
        const float* __restrict__ bn2,
        float* __restrict__ out) {
    __shared__ __align__(16) float sIn[16 * 132];
    __shared__ __align__(16) float sH1[16 * 68];
    int tid = threadIdx.x;
    int nodeBase = blockIdx.x * 16;

#pragma unroll
    for (int it = 0; it < 2; ++it) {
        int item = it * 256 + tid;
        int n = item >> 5;
        int q = item & 31;
        float4 v = (q < 16)
            ? __ldg((const float4*)(nf + (size_t)(nodeBase + n) * F) + q)
            : *(const float4*)(g_hneigh + (size_t)(nodeBase + n) * F + (q - 16) * 4);
        *(float4*)(sIn + n * 132 + q * 4) = v;
    }
    __syncthreads();

    int n  = tid >> 4;
    int cq = (tid & 15) * 4;
    const float* xrow = sIn + n * 132;

    u64p a0, a1;
    {
        float4 b = __ldg((const float4*)(bn1 + cq));
        a0 = pack2(b.x, b.y); a1 = pack2(b.z, b.w);
    }
#pragma unroll 8
    for (int k = 0; k < 128; ++k) {
        float x = xrow[k];
        u64p xp = pack2(x, x);
        ulonglong2 w = __ldg((const ulonglong2*)(Wn1 + k * F + cq));
        ffma2(a0, xp, w.x); ffma2(a1, xp, w.y);
    }
    {
        float v0, v1, v2, v3;
        unpack2(a0, v0, v1); unpack2(a1, v2, v3);
        *(float4*)(sH1 + n * 68 + cq) =
            make_float4(siluf(v0), siluf(v1), siluf(v2), siluf(v3));
    }
    __syncthreads();

    const float* hrow = sH1 + n * 68;
    {
        float4 b = __ldg((const float4*)(bn2 + cq));
        a0 = pack2(b.x, b.y); a1 = pack2(b.z, b.w);
    }
#pragma unroll 8
    for (int k = 0; k < 64; ++k) {
        float x = hrow[k];
        u64p xp = pack2(x, x);
        ulonglong2 w = __ldg((const ulonglong2*)(Wn2 + k * F + cq));
        ffma2(a0, xp, w.x); ffma2(a1, xp, w.y);
    }
    float v0, v1, v2, v3;
    unpack2(a0, v0, v1); unpack2(a1, v2, v3);
    *(float4*)(out + (size_t)(nodeBase + n) * F + cq) = make_float4(v0, v1, v2, v3);
}

extern "C" void kernel_launch(void* const* d_in, const int* in_sizes, int n_in,
                              void* d_out, int out_size) {
    const float* nf    = (const float*)d_in[0];
    const float* coord = (const float*)d_in[1];
    const float* efeat = (const float*)d_in[2];
    const float* We1   = (const float*)d_in[3];
    const float* be1   = (const float*)d_in[4];
    const float* We2   = (const float*)d_in[5];
    const float* be2   = (const float*)d_in[6];
    const float* Wn1   = (const float*)d_in[7];
    const float* bn1   = (const float*)d_in[8];
    const float* Wn2   = (const float*)d_in[9];
    const float* bn2   = (const float*)d_in[10];
    const float* Wq    = (const float*)d_in[11];
    const float* Wk    = (const float*)d_in[12];
    const int*   src   = (const int*)d_in[13];
    const int*   dst   = (const int*)d_in[14];
    float* out = (float*)d_out;

    const int k3_smem = SM_FLOATS * (int)sizeof(float);
    cudaFuncSetAttribute(k3_message, cudaFuncAttributeMaxDynamicSharedMemorySize, k3_smem);

    k0_node_pre<<<NN / 4, 256>>>(nf, We1, Wk, Wq);
    k1_scores<<<EE / 128, 256>>>(coord, efeat, src, dst);
    k3_message<<<EE / EPB, 256, k3_smem>>>(efeat, We1, be1, We2, be2, src, dst);
    k4_node<<<NN / 16, 256>>>(nf, Wn1, bn1, Wn2, bn2, out);
}

// round 16
// speedup vs baseline: 1.5964x; 1.0266x over previous
#include <cuda_runtime.h>
#include <cuda_fp16.h>
#include <stdint.h>
#include <math.h>

#define NN 10000
#define EE 640000
#define F  64
#define EFD 16

typedef unsigned long long u64p;

// ---- scratch (device globals; no allocations allowed) ----
__device__ __half g_Asrc16[NN*F];
__device__ __half g_Adst16[NN*F];
__device__ __half g_Kn16[NN*F];
__device__ __half g_Qn16[NN*F];
__device__ float g_Qk[NN*EFD];
__device__ float g_qd2[NN];
__device__ float g_denom[NN];
__device__ float g_hneigh[NN*F];
__device__ float g_e[EE];      // holds exp(score) after K1
__device__ float g_dist[EE];

__device__ __forceinline__ float siluf(float x) { return x / (1.f + __expf(-x)); }

__device__ __forceinline__ void redAdd4(float* addr, float a, float b, float c, float d) {
    asm volatile("red.global.add.v4.f32 [%0], {%1,%2,%3,%4};"
                 :: "l"(addr), "f"(a), "f"(b), "f"(c), "f"(d) : "memory");
}

__device__ __forceinline__ u64p pack2(float x, float y) {
    u64p r; asm("mov.b64 %0, {%1,%2};" : "=l"(r) : "f"(x), "f"(y)); return r;
}
__device__ __forceinline__ void unpack2(u64p v, float& x, float& y) {
    asm("mov.b64 {%0,%1}, %2;" : "=f"(x), "=f"(y) : "l"(v));
}
__device__ __forceinline__ void ffma2(u64p& d, u64p a, u64p b) {
    asm("fma.rn.f32x2 %0, %1, %2, %0;" : "+l"(d) : "l"(a), "l"(b));
}

__device__ __forceinline__ uint32_t smem_u32(const void* p) {
    uint32_t a;
    asm("{ .reg .u64 t; cvta.to.shared.u64 t, %1; cvt.u32.u64 %0, t; }" : "=r"(a) : "l"(p));
    return a;
}
__device__ __forceinline__ uint32_t swz128(uint32_t x) { return x ^ ((x >> 3) & 0x70u); }
__device__ __forceinline__ uint32_t swz64(uint32_t x)  { return x ^ ((x >> 3) & 0x30u); }

__device__ __forceinline__ void ldmx4(uint32_t& a0, uint32_t& a1, uint32_t& a2, uint32_t& a3,
                                      uint32_t addr) {
    asm volatile("ldmatrix.sync.aligned.m8n8.x4.shared.b16 {%0,%1,%2,%3}, [%4];"
                 : "=r"(a0), "=r"(a1), "=r"(a2), "=r"(a3) : "r"(addr));
}
__device__ __forceinline__ void ldmx2t(uint32_t& b0, uint32_t& b1, uint32_t addr) {
    asm volatile("ldmatrix.sync.aligned.m8n8.x2.trans.shared.b16 {%0,%1}, [%2];"
                 : "=r"(b0), "=r"(b1) : "r"(addr));
}
__device__ __forceinline__ void mma16816(float& d0, float& d1, float& d2, float& d3,
                                         uint32_t a0, uint32_t a1, uint32_t a2, uint32_t a3,
                                         uint32_t b0, uint32_t b1) {
    asm volatile("mma.sync.aligned.m16n8k16.row.col.f32.f16.f16.f32 "
                 "{%0,%1,%2,%3}, {%4,%5,%6,%7}, {%8,%9}, {%0,%1,%2,%3};"
                 : "+f"(d0), "+f"(d1), "+f"(d2), "+f"(d3)
                 : "r"(a0), "r"(a1), "r"(a2), "r"(a3), "r"(b0), "r"(b1));
}

// ================= K0: per-node precompute (fp16 tables) + init =================
__global__ void k0_node_pre(const float* __restrict__ nf,
                            const float* __restrict__ We1,
                            const float* __restrict__ Wk,
                            const float* __restrict__ Wq) {
    __shared__ __align__(16) float srow[4 * F];
    __shared__ __align__(16) float sQ[4 * F];
    int tid = threadIdx.x;
    int nodeBase = blockIdx.x * 4;
    srow[tid] = nf[(size_t)nodeBase * F + tid];
    __syncthreads();
    int ln = tid >> 6;
    int c  = tid & 63;
    int node = nodeBase + ln;
    const float* r = srow + ln * F;
    float a0 = 0.f, a1 = 0.f, a2 = 0.f, a3 = 0.f;
#pragma unroll 8
    for (int k = 0; k < F; ++k) {
        float x = r[k];
        a0 += x * __ldg(We1 + k * F + c);
        a1 += x * __ldg(We1 + (F + k) * F + c);
        a2 += x * __ldg(Wk  + k * F + c);
        a3 += x * __ldg(Wq  + k * F + c);
    }
    g_Asrc16[node * F + c] = __float2half_rn(a0);
    g_Adst16[node * F + c] = __float2half_rn(a1);
    g_Kn16  [node * F + c] = __float2half_rn(a2);
    g_Qn16  [node * F + c] = __float2half_rn(a3);
    sQ[ln * F + c] = a3;
    g_hneigh[node * F + c] = 0.f;
    if (c == 0) g_denom[node] = 0.f;
    __syncthreads();
    if (tid < 64) {
        int ln2 = tid >> 4, j = tid & 15;
        const float* q = sQ + ln2 * F;
        float acc = 0.f;
#pragma unroll 8
        for (int k = 0; k < F; ++k) acc += q[k] * __ldg(Wk + (65 + j) * F + k);
        g_Qk[(nodeBase + ln2) * EFD + j] = acc;
    } else if (tid < 68) {
        int ln2 = tid - 64;
        const float* q = sQ + ln2 * F;
        float acc = 0.f;
#pragma unroll 8
        for (int k = 0; k < F; ++k) acc += q[k] * __ldg(Wk + 64 * F + k);
        g_qd2[nodeBase + ln2] = acc;
    }
}

// ================= K1: edge scores -> exp(e), denom atomicAdd (fp16 gathers) =================
__global__ void __launch_bounds__(256)
k1_scores(const float* __restrict__ coord,
          const float* __restrict__ efeat,
          const int* __restrict__ src,
          const int* __restrict__ dst) {
    int tid = threadIdx.x;
    int warp = tid >> 5, lane = tid & 31;
    int sub = lane >> 4, c = lane & 15;
    int base = blockIdx.x * 128 + warp * 16;

#pragma unroll
    for (int it = 0; it < 8; ++it) {
        int e = base + it * 2 + sub;
        int s = __ldg(&src[e]);
        int d = __ldg(&dst[e]);

        uint2 ku = __ldg((const uint2*)(g_Kn16 + (size_t)s * F) + c);
        uint2 qu = __ldg((const uint2*)(g_Qn16 + (size_t)d * F) + c);
        float2 k0 = __half22float2(*(__half2*)&ku.x);
        float2 k1 = __half22float2(*(__half2*)&ku.y);
        float2 q0 = __half22float2(*(__half2*)&qu.x);
        float2 q1 = __half22float2(*(__half2*)&qu.y);
        float part = k0.x * q0.x + k0.y * q0.y + k1.x * q1.x + k1.y * q1.y;

        if (c < 4) {
            float4 ev = __ldg((const float4*)(efeat + (size_t)e * EFD) + c);
            float4 qk = __ldg((const float4*)(g_Qk + (size_t)d * EFD) + c);
            part += ev.x * qk.x + ev.y * qk.y + ev.z * qk.z + ev.w * qk.w;
        }

        float dist = 0.f;
        if (c == 0) {
            float dx = __ldg(&coord[s * 3 + 0]) - __ldg(&coord[d * 3 + 0]);
            float dy = __ldg(&coord[s * 3 + 1]) - __ldg(&coord[d * 3 + 1]);
            float dz = __ldg(&coord[s * 3 + 2]) - __ldg(&coord[d * 3 + 2]);
            dist = sqrtf(dx * dx + dy * dy + dz * dz);
            part += dist * __ldg(&g_qd2[d]);
        }

#pragma unroll
        for (int o = 8; o; o >>= 1)
            part += __shfl_down_sync(0xffffffffu, part, o, 16);

        if (c == 0) {
            float v = __expf(part * 0.125f);
            g_e[e] = v;
            g_dist[e] = dist;
            atomicAdd(&g_denom[d], v);
        }
    }
}

// ================= K3: dual mma.sync edge message + scatter (fp16 gathers) =================
// 128 edges/block, 256 threads, 38.4KB smem -> 4 blocks/SM.
// byte layout:
//   [0,16384)      A-tile fp16 [128e][64h], SW128 (gather writes pre; Phase A RMW -> h1)
//   [16384,24576)  B-tile fp16 [64h][64c], SW128 (We2)
//   [24576,28672)  Wa fp16 [32k][64h], SW128 (k0-15 ef rows, k16 dist row, rest 0)
//   [28672,36864)  efx fp16 [128e][32k], 64B rows SW64 (k0-15 ef, k16 dist, rest 0)
//   epilogue SCR [16 c4][516] fl overlays bytes [0,33024) after Phase B
//   floats >= 9216: att[128], dst[128], b1[64], b2[64]
#define EPB 128
#define GSTRIDE 516
#define SM_B_BYTE   16384
#define SM_WA_BYTE  24576
#define SM_EFX_BYTE 28672
#define SM_ATT_FLT  9216
#define SM_DST_FLT  9344
#define SM_B1_FLT   9472
#define SM_B2_FLT   9536
#define SM_FLOATS   9600

__global__ void __launch_bounds__(256, 4)
k3_message(const float* __restrict__ efeat,
           const float* __restrict__ We1,
           const float* __restrict__ be1,
           const float* __restrict__ We2,
           const float* __restrict__ be2,
           const int* __restrict__ src,
           const int* __restrict__ dst) {
    extern __shared__ __align__(1024) float sm[];
    char* smb = (char*)sm;
    float* sAtt  = sm + SM_ATT_FLT;
    int*   sDstA = (int*)(sm + SM_DST_FLT);
    float* sB1   = sm + SM_B1_FLT;
    float* sB2   = sm + SM_B2_FLT;

    int tid = threadIdx.x;
    int lane = tid & 31;
    int wid = tid >> 5;
    int blockbase = blockIdx.x * EPB;
    uint32_t sbase = smem_u32(sm);

    // ---- stage Wa fp16 [32k][64h]: k0-15 = We1[129+k], k16 = We1[128], rest 0 ----
#pragma unroll
    for (int it = 0; it < 8; ++it) {
        int i = it * 256 + tid;      // 0..2047
        int k = i >> 6, h = i & 63;
        float v = (k < 16) ? We1[(129 + k) * F + h]
                           : (k == 16 ? We1[128 * F + h] : 0.f);
        *(__half*)(smb + SM_WA_BYTE + swz128((uint32_t)(k * 128 + h * 2))) =
            __float2half_rn(v);
    }
    if (tid >= 192) {
        int t = tid - 192;
        sB1[t] = be1[t];
        sB2[t] = be2[t];
    }
    // ---- per-edge scalars + efx upper half-row (k16 = dist, k17-31 = 0) ----
    if (tid < 128) {
        int e = blockbase + tid;
        int d = __ldg(&dst[e]);
        sDstA[tid] = d;
        sAtt[tid] = __fdividef(__ldg(&g_e[e]), __ldg(&g_denom[d]));
        float dist = __ldg(&g_dist[e]);
        __half2 dz = __floats2half2_rn(dist, 0.f);
        uint4 u0;
        u0.x = *(uint32_t*)&dz; u0.y = 0; u0.z = 0; u0.w = 0;
        *(uint4*)(smb + SM_EFX_BYTE + swz64((uint32_t)(tid * 64 + 32))) = u0;
        uint4 z; z.x = z.y = z.z = z.w = 0;
        *(uint4*)(smb + SM_EFX_BYTE + swz64((uint32_t)(tid * 64 + 48))) = z;
    }
    // ---- efx lower half: k0-15 = efeat fp16 ----
#pragma unroll
    for (int it = 0; it < 2; ++it) {
        int item = it * 256 + tid;   // 0..511
        int e = item >> 2;
        int c = item & 3;
        float4 v = __ldg((const float4*)(efeat + (size_t)(blockbase + e) * EFD) + c);
        __half2 h0 = __floats2half2_rn(v.x, v.y);
        __half2 h1 = __floats2half2_rn(v.z, v.w);
        uint2 u;
        u.x = *(uint32_t*)&h0;
        u.y = *(uint32_t*)&h1;
        *(uint2*)(smb + SM_EFX_BYTE + swz64((uint32_t)(e * 64 + c * 8))) = u;
    }
    // ---- stage B-tile: We2 [h][c] fp16, SW128 ----
#pragma unroll
    for (int it = 0; it < 16; ++it) {
        int i = it * 256 + tid;      // 0..4095
        int h = i >> 6, c = i & 63;
        *(__half*)(smb + SM_B_BYTE + swz128((uint32_t)(h * 128 + c * 2))) =
            __float2half_rn(We2[h * F + c]);
    }
    // ---- coalesced fp16 gather of pre = Asrc[s]+Adst[d] into A-tile ----
#pragma unroll
    for (int it = 0; it < 8; ++it) {
        int item = it * 256 + tid;   // 0..2047
        int e = item >> 4;
        int c = item & 15;           // 4-h group
        int s = __ldg(&src[blockbase + e]);
        int d = __ldg(&dst[blockbase + e]);
        uint2 ua = __ldg((const uint2*)(g_Asrc16 + (size_t)s * F) + c);
        uint2 ub = __ldg((const uint2*)(g_Adst16 + (size_t)d * F) + c);
        __half2 s0 = __hadd2(*(__half2*)&ua.x, *(__half2*)&ub.x);
        __half2 s1 = __hadd2(*(__half2*)&ua.y, *(__half2*)&ub.y);
        uint2 u;
        u.x = *(uint32_t*)&s0;
        u.y = *(uint32_t*)&s1;
        *(uint2*)(smb + swz128((uint32_t)(e * 128 + c * 8))) = u;
    }
    __syncthreads();

    int ew = wid * 16;

    // ---------------- Phase A: mma.sync, warp = 16e x 64h, K=32 ----------------
    {
        float pacc[8][4];
#pragma unroll
        for (int j = 0; j < 8; ++j)
            pacc[j][0] = pacc[j][1] = pacc[j][2] = pacc[j][3] = 0.f;

        uint32_t arow = (uint32_t)((ew + (lane & 15)) * 64) + ((lane >> 4) << 4);
        uint32_t brow = (uint32_t)((lane & 15) * 128);
#pragma unroll
        for (int kk = 0; kk < 2; ++kk) {
            uint32_t a0, a1, a2, a3;
            ldmx4(a0, a1, a2, a3, sbase + SM_EFX_BYTE + swz64(arow + kk * 32));
#pragma unroll
            for (int j = 0; j < 8; ++j) {
                uint32_t b0, b1;
                ldmx2t(b0, b1, sbase + SM_WA_BYTE + swz128(brow + kk * 16 * 128 + j * 16));
                mma16816(pacc[j][0], pacc[j][1], pacc[j][2], pacc[j][3],
                         a0, a1, a2, a3, b0, b1);
            }
        }

        // h1 = silu(pre + b1 + acc), RMW in A-tile at D-fragment coords
        int g = lane >> 2, tg = lane & 3;
        int r0 = ew + g, r1 = r0 + 8;
#pragma unroll
        for (int j = 0; j < 8; ++j) {
            int c = j * 8 + tg * 2;
            float b1a = sB1[c], b1b = sB1[c + 1];
            char* p0 = smb + swz128((uint32_t)(r0 * 128 + c * 2));
            char* p1 = smb + swz128((uint32_t)(r1 * 128 + c * 2));
            float2 f0 = __half22float2(*(__half2*)p0);
            float2 f1 = __half22float2(*(__half2*)p1);
            __half2 o0 = __floats2half2_rn(siluf(f0.x + pacc[j][0] + b1a),
                                           siluf(f0.y + pacc[j][1] + b1b));
            __half2 o1 = __floats2half2_rn(siluf(f1.x + pacc[j][2] + b1a),
                                           siluf(f1.y + pacc[j][3] + b1b));
            *(__half2*)p0 = o0;
            *(__half2*)p1 = o1;
        }
    }
    __syncthreads();

    // ---------------- Phase B: mma.sync, warp = 16e x 64c ----------------
    float acc[8][4];
#pragma unroll
    for (int j = 0; j < 8; ++j)
        acc[j][0] = acc[j][1] = acc[j][2] = acc[j][3] = 0.f;

    {
        uint32_t arow = (uint32_t)((ew + (lane & 15)) * 128) + ((lane >> 4) << 4);
        uint32_t brow = (uint32_t)((lane & 15) * 128);
#pragma unroll
        for (int kk = 0; kk < 4; ++kk) {
            uint32_t a0, a1, a2, a3;
            ldmx4(a0, a1, a2, a3, sbase + swz128(arow + kk * 32));
#pragma unroll
            for (int j = 0; j < 8; ++j) {
                uint32_t b0, b1;
                ldmx2t(b0, b1, sbase + SM_B_BYTE + swz128(brow + kk * 16 * 128 + j * 16));
                mma16816(acc[j][0], acc[j][1], acc[j][2], acc[j][3],
                         a0, a1, a2, a3, b0, b1);
            }
        }
    }
    __syncthreads();   // A/B tiles dead; epilogue overlays them

    // ---- epilogue: silu(d + b2) * att into SCR [c4][e][4] ----
    {
        int g = lane >> 2;
        int tg = lane & 3;
        int r0 = ew + g, r1 = r0 + 8;
        float att0 = sAtt[r0], att1 = sAtt[r1];
#pragma unroll
        for (int j = 0; j < 8; ++j) {
            int c = j * 8 + tg * 2;
            float b2a = sB2[c], b2b = sB2[c + 1];
            float* base = sm + (c >> 2) * GSTRIDE + (c & 3);
            *(float2*)(base + r0 * 4) =
                make_float2(siluf(acc[j][0] + b2a) * att0, siluf(acc[j][1] + b2b) * att0);
            *(float2*)(base + r1 * 4) =
                make_float2(siluf(acc[j][2] + b2a) * att1, siluf(acc[j][3] + b2b) * att1);
        }
    }
    __syncthreads();

    // ---- coalesced REDG scatter ----
#pragma unroll
    for (int it = 0; it < 8; ++it) {
        int item = it * 256 + tid;   // 0..2047
        int e = item >> 4;
        int c = item & 15;
        float4 v = *(const float4*)(sm + c * GSTRIDE + e * 4);
        redAdd4(g_hneigh + (size_t)sDstA[e] * F + c * 4, v.x, v.y, v.z, v.w);
    }
}

// ================= K4: node MLP — FFMA2, 4 channels/thread, 16 nodes/block =================
__global__ void __launch_bounds__(256)
k4_node(const float* __restrict__ nf,
        const float* __restrict__ Wn1,
        const float* __restrict__ bn1,
        const float* __restrict__ Wn2,
        const float* __restrict__ bn2,
        float* __restrict__ out) {
    __shared__ __align__(16) float sIn[16 * 132];
    __shared__ __align__(16) float sH1[16 * 68];
    int tid = threadIdx.x;
    int nodeBase = blockIdx.x * 16;

#pragma unroll
    for (int it = 0; it < 2; ++it) {
        int item = it * 256 + tid;
        int n = item >> 5;
        int q = item & 31;
        float4 v = (q < 16)
            ? __ldg((const float4*)(nf + (size_t)(nodeBase + n) * F) + q)
            : *(const float4*)(g_hneigh + (size_t)(nodeBase + n) * F + (q - 16) * 4);
        *(float4*)(sIn + n * 132 + q * 4) = v;
    }
    __syncthreads();

    int n  = tid >> 4;
    int cq = (tid & 15) * 4;
    const float* xrow = sIn + n * 132;

    u64p a0, a1;
    {
        float4 b = __ldg((const float4*)(bn1 + cq));
        a0 = pack2(b.x, b.y); a1 = pack2(b.z, b.w);
    }
#pragma unroll 8
    for (int k = 0; k < 128; ++k) {
        float x = xrow[k];
        u64p xp = pack2(x, x);
        ulonglong2 w = __ldg((const ulonglong2*)(Wn1 + k * F + cq));
        ffma2(a0, xp, w.x); ffma2(a1, xp, w.y);
    }
    {
        float v0, v1, v2, v3;
        unpack2(a0, v0, v1); unpack2(a1, v2, v3);
        *(float4*)(sH1 + n * 68 + cq) =
            make_float4(siluf(v0), siluf(v1), siluf(v2), siluf(v3));
    }
    __syncthreads();

    const float* hrow = sH1 + n * 68;
    {
        float4 b = __ldg((const float4*)(bn2 + cq));
        a0 = pack2(b.x, b.y); a1 = pack2(b.z, b.w);
    }
#pragma unroll 8
    for (int k = 0; k < 64; ++k) {
        float x = hrow[k];
        u64p xp = pack2(x, x);
        ulonglong2 w = __ldg((const ulonglong2*)(Wn2 + k * F + cq));
        ffma2(a0, xp, w.x); ffma2(a1, xp, w.y);
    }
    float v0, v1, v2, v3;
    unpack2(a0, v0, v1); unpack2(a1, v2, v3);
    *(float4*)(out + (size_t)(nodeBase + n) * F + cq) = make_float4(v0, v1, v2, v3);
}

extern "C" void kernel_launch(void* const* d_in, const int* in_sizes, int n_in,
                              void* d_out, int out_size) {
    const float* nf    = (const float*)d_in[0];
    const float* coord = (const float*)d_in[1];
    const float* efeat = (const float*)d_in[2];
    const float* We1   = (const float*)d_in[3];
    const float* be1   = (const float*)d_in[4];
    const float* We2   = (const float*)d_in[5];
    const float* be2   = (const float*)d_in[6];
    const float* Wn1   = (const float*)d_in[7];
    const float* bn1   = (const float*)d_in[8];
    const float* Wn2   = (const float*)d_in[9];
    const float* bn2   = (const float*)d_in[10];
    const float* Wq    = (const float*)d_in[11];
    const float* Wk    = (const float*)d_in[12];
    const int*   src   = (const int*)d_in[13];
    const int*   dst   = (const int*)d_in[14];
    float* out = (float*)d_out;

    const int k3_smem = SM_FLOATS * (int)sizeof(float);
    cudaFuncSetAttribute(k3_message, cudaFuncAttributeMaxDynamicSharedMemorySize, k3_smem);

    k0_node_pre<<<NN / 4, 256>>>(nf, We1, Wk, Wq);
    k1_scores<<<EE / 128, 256>>>(coord, efeat, src, dst);
    k3_message<<<EE / EPB, 256, k3_smem>>>(efeat, We1, be1, We2, be2, src, dst);
    k4_node<<<NN / 16, 256>>>(nf, Wn1, bn1, Wn2, bn2, out);
}